// round 4
// baseline (speedup 1.0000x reference)
#include <cuda_runtime.h>
#include <cuda_bf16.h>
#include <math.h>
#include <stdint.h>

#define Bn 16384
#define Dn 512
#define Kn 16384
#define Hn 256
#define Zn 128

// ---------------- scratch ----------------
__device__ __align__(16) __nv_bfloat16 g_Ebuf[(size_t)Bn * 384];  // [e0|e1|e2]
__device__ __align__(16) __nv_bfloat16 g_Cbuf[(size_t)Kn * 384];  // [c0|c1|c2]
__device__ float g_c2h[Kn];
__device__ int   g_idx[Bn];
__device__ float g_err[Bn];
__device__ float g_sum;

// ---------------- warp MMA helpers (base sm_103 target safe) ----------------
__device__ __forceinline__ uint32_t smem_u32(const void* p) {
    uint32_t a;
    asm("{ .reg .u64 t; cvta.to.shared.u64 t, %1; cvt.u32.u64 %0, t; }" : "=r"(a) : "l"(p));
    return a;
}
__device__ __forceinline__ void ldsm_x4(uint32_t r[4], uint32_t addr) {
    asm volatile("ldmatrix.sync.aligned.m8n8.x4.shared.b16 {%0,%1,%2,%3}, [%4];"
        : "=r"(r[0]), "=r"(r[1]), "=r"(r[2]), "=r"(r[3]) : "r"(addr));
}
__device__ __forceinline__ void mma_bf16(float d[4], const uint32_t a[4], const uint32_t b[2]) {
    asm volatile("mma.sync.aligned.m16n8k16.row.col.f32.bf16.bf16.f32 "
        "{%0,%1,%2,%3}, {%4,%5,%6,%7}, {%8,%9}, {%0,%1,%2,%3};"
        : "+f"(d[0]), "+f"(d[1]), "+f"(d[2]), "+f"(d[3])
        : "r"(a[0]), "r"(a[1]), "r"(a[2]), "r"(a[3]), "r"(b[0]), "r"(b[1]));
}

// ---------------- encoder: X@W1+b1 -> LN -> GELU -> @W2+b2 -> bf16 3-split ----------------
__global__ void encoder_kernel(const float* __restrict__ X,
                               const float* __restrict__ W1, const float* __restrict__ b1,
                               const float* __restrict__ g1, const float* __restrict__ be1,
                               const float* __restrict__ W2, const float* __restrict__ b2)
{
    extern __shared__ float sm[];
    float* Xs = sm;
    float* Hs = sm + 32 * Dn;
    const int tid = threadIdx.x;
    const int row0 = blockIdx.x * 32;

    {
        const float4* Xg = (const float4*)(X + (size_t)row0 * Dn);
        float4* Xs4 = (float4*)Xs;
        for (int i = tid; i < 32 * Dn / 4; i += 256) Xs4[i] = Xg[i];
    }
    __syncthreads();

    const float4* Xs4 = (const float4*)Xs;
    float acc[32];
#pragma unroll
    for (int r = 0; r < 32; ++r) acc[r] = 0.f;
    const int col = tid;
    for (int d = 0; d < Dn; d += 4) {
        float w0 = W1[(d + 0) * Hn + col];
        float w1 = W1[(d + 1) * Hn + col];
        float w2 = W1[(d + 2) * Hn + col];
        float w3 = W1[(d + 3) * Hn + col];
#pragma unroll
        for (int r = 0; r < 32; ++r) {
            float4 x = Xs4[(r * Dn + d) >> 2];
            acc[r] = fmaf(x.x, w0, acc[r]);
            acc[r] = fmaf(x.y, w1, acc[r]);
            acc[r] = fmaf(x.z, w2, acc[r]);
            acc[r] = fmaf(x.w, w3, acc[r]);
        }
    }
    {
        float bb = b1[col];
#pragma unroll
        for (int r = 0; r < 32; ++r) Hs[r * Hn + col] = acc[r] + bb;
    }
    __syncthreads();

    {
        const int warp = tid >> 5, lane = tid & 31;
        for (int rr = 0; rr < 4; ++rr) {
            int r = warp + rr * 8;
            float s = 0.f, s2 = 0.f;
#pragma unroll
            for (int j = 0; j < 8; ++j) {
                float v = Hs[r * Hn + lane + j * 32];
                s += v; s2 += v * v;
            }
#pragma unroll
            for (int o = 16; o > 0; o >>= 1) {
                s  += __shfl_xor_sync(0xffffffff, s,  o);
                s2 += __shfl_xor_sync(0xffffffff, s2, o);
            }
            float mu  = s * (1.f / Hn);
            float var = s2 * (1.f / Hn) - mu * mu;
            float inv = rsqrtf(var + 1e-5f);
#pragma unroll
            for (int j = 0; j < 8; ++j) {
                int c = lane + j * 32;
                float v = (Hs[r * Hn + c] - mu) * inv * g1[c] + be1[c];
                Hs[r * Hn + c] = 0.5f * v * (1.f + erff(v * 0.70710678118654752f));
            }
        }
    }
    __syncthreads();

    {
        const float4* Hs4 = (const float4*)Hs;
        const int c2 = tid & 127;
        const int rbase = (tid >> 7) * 16;
        float a2[16];
#pragma unroll
        for (int r = 0; r < 16; ++r) a2[r] = 0.f;
        for (int d = 0; d < Hn; d += 4) {
            float w0 = W2[(d + 0) * Zn + c2];
            float w1 = W2[(d + 1) * Zn + c2];
            float w2 = W2[(d + 2) * Zn + c2];
            float w3 = W2[(d + 3) * Zn + c2];
#pragma unroll
            for (int r = 0; r < 16; ++r) {
                float4 h = Hs4[((rbase + r) * Hn + d) >> 2];
                a2[r] = fmaf(h.x, w0, a2[r]);
                a2[r] = fmaf(h.y, w1, a2[r]);
                a2[r] = fmaf(h.z, w2, a2[r]);
                a2[r] = fmaf(h.w, w3, a2[r]);
            }
        }
        float bb = b2[c2];
#pragma unroll
        for (int r = 0; r < 16; ++r) {
            float e = a2[r] + bb;
            __nv_bfloat16 e0 = __float2bfloat16(e);
            float f0 = __bfloat162float(e0);
            __nv_bfloat16 e1 = __float2bfloat16(e - f0);
            float f1 = __bfloat162float(e1);
            __nv_bfloat16 e2 = __float2bfloat16(e - f0 - f1);
            size_t base = (size_t)(row0 + rbase + r) * 384 + c2;
            g_Ebuf[base]       = e0;
            g_Ebuf[base + 128] = e1;
            g_Ebuf[base + 256] = e2;
        }
    }
}

// ---------------- codebook 3-way split ----------------
__global__ void csplit_kernel(const float* __restrict__ C)
{
    int i = blockIdx.x * 256 + threadIdx.x;
    int row = i >> 7, col = i & 127;
    float v = C[i];
    __nv_bfloat16 c0 = __float2bfloat16(v);
    float f0 = __bfloat162float(c0);
    __nv_bfloat16 c1 = __float2bfloat16(v - f0);
    float f1 = __bfloat162float(c1);
    __nv_bfloat16 c2 = __float2bfloat16(v - f0 - f1);
    size_t base = (size_t)row * 384 + col;
    g_Cbuf[base]       = c0;
    g_Cbuf[base + 128] = c1;
    g_Cbuf[base + 256] = c2;
}

// ---------------- 0.5*||c||^2 ----------------
__global__ void c2_kernel(const float* __restrict__ C)
{
    int gt = blockIdx.x * 256 + threadIdx.x;
    int code = gt >> 5, lane = gt & 31;
    float4 v = ((const float4*)C)[code * 32 + lane];
    float s = v.x * v.x + v.y * v.y + v.z * v.z + v.w * v.w;
#pragma unroll
    for (int o = 16; o > 0; o >>= 1) s += __shfl_xor_sync(0xffffffff, s, o);
    if (lane == 0) g_c2h[code] = 0.5f * s;
}

// ---------------- tensor-core distance argmax (mma.sync bf16) ----------------
// CTA: 128 rows x full K. Per tile: 128 codes.
// SMEM rows padded to 392 bf16 (784B) -> conflict-free ldmatrix.
#define LDK  392
#define SB_A 0
#define SB_B (128 * LDK * 2)
#define SB_C2 (2 * 128 * LDK * 2)
#define DSM_TOT (SB_C2 + 512)

__global__ __launch_bounds__(256, 1) void dist_mma_kernel()
{
    extern __shared__ char smem[];
    __nv_bfloat16* As = (__nv_bfloat16*)(smem + SB_A);
    __nv_bfloat16* Bs = (__nv_bfloat16*)(smem + SB_B);
    float* c2s = (float*)(smem + SB_C2);

    const int tid  = threadIdx.x;
    const int lane = tid & 31;
    const int wid  = tid >> 5;
    const int warp_m = wid >> 2;       // 0..1 (64-row bands)
    const int warp_n = wid & 3;        // 0..3 (32-col bands)
    const int row0 = blockIdx.x * 128;

    const uint32_t sbA = smem_u32(As);
    const uint32_t sbB = smem_u32(Bs);

    // load resident A split (128 rows x 384 bf16) into padded smem
    for (int i = tid; i < 128 * 48; i += 256) {
        int r = i / 48, u = i % 48;
        uint4 v = ((const uint4*)(g_Ebuf + (size_t)(row0 + r) * 384))[u];
        *(uint4*)((char*)As + r * (LDK * 2) + u * 16) = v;
    }

    // per-thread A/B ldmatrix base addressing
    // A: row = warp_m*64 + mi*16 + (lane&15), kofs += (lane>>4)*8
    uint32_t a_addr[4];
#pragma unroll
    for (int mi = 0; mi < 4; ++mi)
        a_addr[mi] = sbA + ((warp_m * 64 + mi * 16 + (lane & 15)) * LDK + (lane >> 4) * 8) * 2;
    // B (non-trans x4): matrices {0,1}=codes 0-7 @k{0,8}, {2,3}=codes 8-15 @k{0,8}
    // row(code) = warp_n*32 + njp*16 + ((lane>>4)<<3) + (lane&7), kofs = ((lane>>3)&1)*8
    uint32_t b_addr[2];
#pragma unroll
    for (int njp = 0; njp < 2; ++njp)
        b_addr[njp] = sbB + ((warp_n * 32 + njp * 16 + (lane & 7) + ((lane >> 4) << 3)) * LDK
                             + ((lane >> 3) & 1) * 8) * 2;

    // running argmax state: 8 rows per thread (mi x h)
    float best[8];
    int   bidx[8];
#pragma unroll
    for (int i = 0; i < 8; ++i) { best[i] = -INFINITY; bidx[i] = 0; }

    const int AP[6] = {0, 0, 1, 0, 1, 2};
    const int BP[6] = {0, 1, 0, 2, 1, 0};

    for (int t = 0, kt = 0; t < 128; ++t, kt += 128) {
        __syncthreads();   // previous epilogue done; safe to overwrite Bs/c2s
        // stream B tile (128 codes x 384 bf16)
        for (int i = tid; i < 128 * 48; i += 256) {
            int r = i / 48, u = i % 48;
            uint4 v = ((const uint4*)(g_Cbuf + (size_t)(kt + r) * 384))[u];
            *(uint4*)((char*)Bs + r * (LDK * 2) + u * 16) = v;
        }
        if (tid < 128) c2s[tid] = g_c2h[kt + tid];
        __syncthreads();

        float acc[4][4][4];
#pragma unroll
        for (int mi = 0; mi < 4; ++mi)
#pragma unroll
            for (int nj = 0; nj < 4; ++nj)
#pragma unroll
                for (int k = 0; k < 4; ++k) acc[mi][nj][k] = 0.f;

        for (int p = 0; p < 6; ++p) {
            const uint32_t ka = (uint32_t)(AP[p] * 128) * 2;
            const uint32_t kb = (uint32_t)(BP[p] * 128) * 2;
#pragma unroll
            for (int s = 0; s < 8; ++s) {
                uint32_t af[4][4];
#pragma unroll
                for (int mi = 0; mi < 4; ++mi)
                    ldsm_x4(af[mi], a_addr[mi] + ka + s * 32);
                uint32_t bf[2][4];
#pragma unroll
                for (int njp = 0; njp < 2; ++njp)
                    ldsm_x4(bf[njp], b_addr[njp] + kb + s * 32);
#pragma unroll
                for (int mi = 0; mi < 4; ++mi) {
#pragma unroll
                    for (int nj = 0; nj < 4; ++nj)
                        mma_bf16(acc[mi][nj], af[mi], bf[nj >> 1] + (nj & 1) * 2);
                }
            }
        }

        // epilogue: running argmax over this tile's 128 codes
#pragma unroll
        for (int nj = 0; nj < 4; ++nj) {
            int cbase = warp_n * 32 + nj * 8 + (lane & 3) * 2;
            float c20 = c2s[cbase], c21 = c2s[cbase + 1];
#pragma unroll
            for (int mi = 0; mi < 4; ++mi) {
#pragma unroll
                for (int h = 0; h < 2; ++h) {
                    float s0 = acc[mi][nj][h * 2]     - c20;
                    float s1 = acc[mi][nj][h * 2 + 1] - c21;
                    int ri = mi * 2 + h;
                    if (s0 > best[ri]) { best[ri] = s0; bidx[ri] = kt + cbase; }
                    if (s1 > best[ri]) { best[ri] = s1; bidx[ri] = kt + cbase + 1; }
                }
            }
        }
    }

    // quad reduction (cols within warp), tie -> lower index
#pragma unroll
    for (int ri = 0; ri < 8; ++ri) {
        float v = best[ri]; int ix = bidx[ri];
#pragma unroll
        for (int off = 1; off <= 2; off <<= 1) {
            float ov = __shfl_xor_sync(0xffffffff, v,  off);
            int   oi = __shfl_xor_sync(0xffffffff, ix, off);
            if (ov > v || (ov == v && oi < ix)) { v = ov; ix = oi; }
        }
        best[ri] = v; bidx[ri] = ix;
    }

    // cross-warp reduction via smem (reuse B region)
    __syncthreads();
    float* redv = (float*)(smem + SB_B);
    int*   redi = (int*)(smem + SB_B + 128 * 4 * 4);
    if ((lane & 3) == 0) {
#pragma unroll
        for (int ri = 0; ri < 8; ++ri) {
            int mi = ri >> 1, h = ri & 1;
            int row = warp_m * 64 + mi * 16 + (lane >> 2) + h * 8;
            redv[row * 4 + warp_n] = best[ri];
            redi[row * 4 + warp_n] = bidx[ri];
        }
    }
    __syncthreads();
    if (tid < 128) {
        float bv = redv[tid * 4]; int bi = redi[tid * 4];
#pragma unroll
        for (int w = 1; w < 4; ++w) {
            float v = redv[tid * 4 + w]; int ix = redi[tid * 4 + w];
            if (v > bv || (v == bv && ix < bi)) { bv = v; bi = ix; }
        }
        g_idx[row0 + tid] = bi;
    }
}

// ---------------- decoder ----------------
__global__ void decoder_kernel(const float* __restrict__ C,
                               const float* __restrict__ W3, const float* __restrict__ b3,
                               const float* __restrict__ g2, const float* __restrict__ be2,
                               const float* __restrict__ W4, const float* __restrict__ b4,
                               const float* __restrict__ X)
{
    extern __shared__ float sm[];
    float* Qs = sm;
    float* Hs = sm + 32 * Zn;
    float* ep = Hs + 32 * Hn;
    const int tid = threadIdx.x;
    const int row0 = blockIdx.x * 32;

    for (int i = tid; i < 32 * 32; i += 256) {
        int r = i >> 5, d4 = i & 31;
        int code = g_idx[row0 + r];
        ((float4*)Qs)[r * 32 + d4] = ((const float4*)C)[(size_t)code * 32 + d4];
    }
    __syncthreads();

    {
        const float4* Qs4 = (const float4*)Qs;
        float acc[32];
#pragma unroll
        for (int r = 0; r < 32; ++r) acc[r] = 0.f;
        const int col = tid;
        for (int d = 0; d < Zn; d += 4) {
            float w0 = W3[(d + 0) * Hn + col];
            float w1 = W3[(d + 1) * Hn + col];
            float w2 = W3[(d + 2) * Hn + col];
            float w3 = W3[(d + 3) * Hn + col];
#pragma unroll
            for (int r = 0; r < 32; ++r) {
                float4 q = Qs4[(r * Zn + d) >> 2];
                acc[r] = fmaf(q.x, w0, acc[r]);
                acc[r] = fmaf(q.y, w1, acc[r]);
                acc[r] = fmaf(q.z, w2, acc[r]);
                acc[r] = fmaf(q.w, w3, acc[r]);
            }
        }
        float bb = b3[col];
#pragma unroll
        for (int r = 0; r < 32; ++r) Hs[r * Hn + col] = acc[r] + bb;
    }
    __syncthreads();

    {
        const int warp = tid >> 5, lane = tid & 31;
        for (int rr = 0; rr < 4; ++rr) {
            int r = warp + rr * 8;
            float s = 0.f, s2 = 0.f;
#pragma unroll
            for (int j = 0; j < 8; ++j) {
                float v = Hs[r * Hn + lane + j * 32];
                s += v; s2 += v * v;
            }
#pragma unroll
            for (int o = 16; o > 0; o >>= 1) {
                s  += __shfl_xor_sync(0xffffffff, s,  o);
                s2 += __shfl_xor_sync(0xffffffff, s2, o);
            }
            float mu  = s * (1.f / Hn);
            float var = s2 * (1.f / Hn) - mu * mu;
            float inv = rsqrtf(var + 1e-5f);
#pragma unroll
            for (int j = 0; j < 8; ++j) {
                int c = lane + j * 32;
                float v = (Hs[r * Hn + c] - mu) * inv * g2[c] + be2[c];
                Hs[r * Hn + c] = 0.5f * v * (1.f + erff(v * 0.70710678118654752f));
            }
        }
    }
    __syncthreads();

    float aA[32], aB[32];
#pragma unroll
    for (int r = 0; r < 32; ++r) { aA[r] = 0.f; aB[r] = 0.f; }
    {
        const float4* Hs4 = (const float4*)Hs;
        for (int d = 0; d < Hn; d += 4) {
            float wa0 = W4[(d + 0) * Dn + tid];
            float wa1 = W4[(d + 1) * Dn + tid];
            float wa2 = W4[(d + 2) * Dn + tid];
            float wa3 = W4[(d + 3) * Dn + tid];
            float wb0 = W4[(d + 0) * Dn + tid + 256];
            float wb1 = W4[(d + 1) * Dn + tid + 256];
            float wb2 = W4[(d + 2) * Dn + tid + 256];
            float wb3 = W4[(d + 3) * Dn + tid + 256];
#pragma unroll
            for (int r = 0; r < 32; ++r) {
                float4 h = Hs4[(r * Hn + d) >> 2];
                aA[r] = fmaf(h.x, wa0, aA[r]);
                aA[r] = fmaf(h.y, wa1, aA[r]);
                aA[r] = fmaf(h.z, wa2, aA[r]);
                aA[r] = fmaf(h.w, wa3, aA[r]);
                aB[r] = fmaf(h.x, wb0, aB[r]);
                aB[r] = fmaf(h.y, wb1, aB[r]);
                aB[r] = fmaf(h.z, wb2, aB[r]);
                aB[r] = fmaf(h.w, wb3, aB[r]);
            }
        }
    }

    {
        const int warp = tid >> 5, lane = tid & 31;
        float b4a = b4[tid], b4b = b4[tid + 256];
        for (int r = 0; r < 32; ++r) {
            float f1 = X[(size_t)(row0 + r) * Dn + tid];
            float f2 = X[(size_t)(row0 + r) * Dn + tid + 256];
            float d1 = aA[r] + b4a - f1;
            float d2 = aB[r] + b4b - f2;
            float e = d1 * d1 + d2 * d2;
#pragma unroll
            for (int o = 16; o > 0; o >>= 1) e += __shfl_xor_sync(0xffffffff, e, o);
            if (lane == 0) ep[r * 8 + warp] = e;
        }
        __syncthreads();
        if (tid < 32) {
            float s = 0.f;
#pragma unroll
            for (int w = 0; w < 8; ++w) s += ep[tid * 8 + w];
            g_err[row0 + tid] = s * (1.f / Dn);
        }
    }
}

// ---------------- global mean ----------------
__global__ void reduce_kernel()
{
    __shared__ float s[256];
    int tid = threadIdx.x;
    float a = 0.f;
    for (int i = tid; i < Bn; i += 256) a += g_err[i];
    s[tid] = a;
    __syncthreads();
    for (int o = 128; o > 0; o >>= 1) {
        if (tid < o) s[tid] += s[tid + o];
        __syncthreads();
    }
    if (tid == 0) g_sum = s[0];
}

// ---------------- MDL + output ----------------
__global__ void final_kernel(float* __restrict__ out)
{
    int i = blockIdx.x * 256 + threadIdx.x;
    float scale = g_sum * (1.f / Bn) + 1e-8f;
    float err = g_err[i];
    float eb = (fabsf(err) / scale + logf(2.f * scale)) * 1.4426950408889634f;
    float tb = 14.f + eb;
    out[i]          = err;
    out[Bn + i]     = (Dn * 32.f) / tb;
    out[2 * Bn + i] = tb;
    out[3 * Bn + i] = (float)g_idx[i];
}

// ---------------- launch ----------------
extern "C" void kernel_launch(void* const* d_in, const int* in_sizes, int n_in,
                              void* d_out, int out_size)
{
    const float* X   = (const float*)d_in[0];
    const float* W1  = (const float*)d_in[1];
    const float* b1  = (const float*)d_in[2];
    const float* g1  = (const float*)d_in[3];
    const float* be1 = (const float*)d_in[4];
    const float* W2  = (const float*)d_in[5];
    const float* b2  = (const float*)d_in[6];
    const float* CB  = (const float*)d_in[7];
    const float* W3  = (const float*)d_in[8];
    const float* b3  = (const float*)d_in[9];
    const float* g2  = (const float*)d_in[10];
    const float* be2 = (const float*)d_in[11];
    const float* W4  = (const float*)d_in[12];
    const float* b4  = (const float*)d_in[13];
    float* out = (float*)d_out;

    cudaFuncSetAttribute(encoder_kernel,  cudaFuncAttributeMaxDynamicSharedMemorySize, 98304);
    cudaFuncSetAttribute(dist_mma_kernel, cudaFuncAttributeMaxDynamicSharedMemorySize, DSM_TOT);
    cudaFuncSetAttribute(decoder_kernel,  cudaFuncAttributeMaxDynamicSharedMemorySize, 50176);

    csplit_kernel<<<Kn * Zn / 256, 256>>>(CB);
    c2_kernel<<<Kn / 8, 256>>>(CB);
    encoder_kernel<<<Bn / 32, 256, 98304>>>(X, W1, b1, g1, be1, W2, b2);
    dist_mma_kernel<<<Bn / 128, 256, DSM_TOT>>>();
    decoder_kernel<<<Bn / 32, 256, 50176>>>(CB, W3, b3, g2, be2, W4, b4, X);
    reduce_kernel<<<1, 256>>>();
    final_kernel<<<Bn / 256, 256>>>(out);
}

// round 5
// speedup vs baseline: 1.0421x; 1.0421x over previous
#include <cuda_runtime.h>
#include <cuda_bf16.h>
#include <math.h>
#include <stdint.h>

#define Bn 16384
#define Dn 512
#define Kn 16384
#define Hn 256
#define Zn 128

// ---------------- scratch ----------------
__device__ __align__(16) float g_enc[(size_t)Bn * Zn];          // encoded fp32
__device__ __align__(16) __nv_bfloat16 g_e0[(size_t)Bn * Zn];   // bf16(encoded)
__device__ __align__(16) __nv_bfloat16 g_c0[(size_t)Kn * Zn];   // bf16(codebook)
__device__ float g_c2h[Kn];          // 0.5*||c||^2 exact
__device__ float g_en2[Bn];          // ||e||^2
__device__ float g_dn2[Bn];          // ||e-e0||^2
__device__ float g_Rmax2;            // max_k ||c-c0||^2 (zero-init)
__device__ float g_Nmax2;            // max_k ||c0||^2
__device__ float g_smax[Bn];         // per-row max coarse score
__device__ float g_cand_val[(size_t)Bn * 32];
__device__ int   g_cand_idx[(size_t)Bn * 32];
__device__ float g_third[(size_t)Bn * 16];
__device__ int   g_idx[Bn];
__device__ float g_err[Bn];
__device__ float g_sum;

// ---------------- helpers ----------------
__device__ __forceinline__ uint32_t smem_u32(const void* p) {
    uint32_t a;
    asm("{ .reg .u64 t; cvta.to.shared.u64 t, %1; cvt.u32.u64 %0, t; }" : "=r"(a) : "l"(p));
    return a;
}
__device__ __forceinline__ void ldsm_x4(uint32_t r[4], uint32_t addr) {
    asm volatile("ldmatrix.sync.aligned.m8n8.x4.shared.b16 {%0,%1,%2,%3}, [%4];"
        : "=r"(r[0]), "=r"(r[1]), "=r"(r[2]), "=r"(r[3]) : "r"(addr));
}
__device__ __forceinline__ void mma_bf16(float d[4], const uint32_t a[4], const uint32_t b[2]) {
    asm volatile("mma.sync.aligned.m16n8k16.row.col.f32.bf16.bf16.f32 "
        "{%0,%1,%2,%3}, {%4,%5,%6,%7}, {%8,%9}, {%0,%1,%2,%3};"
        : "+f"(d[0]), "+f"(d[1]), "+f"(d[2]), "+f"(d[3])
        : "r"(a[0]), "r"(a[1]), "r"(a[2]), "r"(a[3]), "r"(b[0]), "r"(b[1]));
}
__device__ __forceinline__ uint32_t pack_bf16(float a, float b) {
    __nv_bfloat162 t = __floats2bfloat162_rn(a, b);
    return *(uint32_t*)&t;
}

// ---------------- encoder: X@W1+b1 -> LN -> GELU -> @W2+b2 (fp32 out) ----------------
__global__ void encoder_kernel(const float* __restrict__ X,
                               const float* __restrict__ W1, const float* __restrict__ b1,
                               const float* __restrict__ g1, const float* __restrict__ be1,
                               const float* __restrict__ W2, const float* __restrict__ b2)
{
    extern __shared__ float sm[];
    float* Xs = sm;
    float* Hs = sm + 32 * Dn;
    const int tid = threadIdx.x;
    const int row0 = blockIdx.x * 32;

    {
        const float4* Xg = (const float4*)(X + (size_t)row0 * Dn);
        float4* Xs4 = (float4*)Xs;
        for (int i = tid; i < 32 * Dn / 4; i += 256) Xs4[i] = Xg[i];
    }
    __syncthreads();

    const float4* Xs4 = (const float4*)Xs;
    float acc[32];
#pragma unroll
    for (int r = 0; r < 32; ++r) acc[r] = 0.f;
    const int col = tid;
    for (int d = 0; d < Dn; d += 4) {
        float w0 = W1[(d + 0) * Hn + col];
        float w1 = W1[(d + 1) * Hn + col];
        float w2 = W1[(d + 2) * Hn + col];
        float w3 = W1[(d + 3) * Hn + col];
#pragma unroll
        for (int r = 0; r < 32; ++r) {
            float4 x = Xs4[(r * Dn + d) >> 2];
            acc[r] = fmaf(x.x, w0, acc[r]);
            acc[r] = fmaf(x.y, w1, acc[r]);
            acc[r] = fmaf(x.z, w2, acc[r]);
            acc[r] = fmaf(x.w, w3, acc[r]);
        }
    }
    {
        float bb = b1[col];
#pragma unroll
        for (int r = 0; r < 32; ++r) Hs[r * Hn + col] = acc[r] + bb;
    }
    __syncthreads();

    {
        const int warp = tid >> 5, lane = tid & 31;
        for (int rr = 0; rr < 4; ++rr) {
            int r = warp + rr * 8;
            float s = 0.f, s2 = 0.f;
#pragma unroll
            for (int j = 0; j < 8; ++j) {
                float v = Hs[r * Hn + lane + j * 32];
                s += v; s2 += v * v;
            }
#pragma unroll
            for (int o = 16; o > 0; o >>= 1) {
                s  += __shfl_xor_sync(0xffffffff, s,  o);
                s2 += __shfl_xor_sync(0xffffffff, s2, o);
            }
            float mu  = s * (1.f / Hn);
            float var = s2 * (1.f / Hn) - mu * mu;
            float inv = rsqrtf(var + 1e-5f);
#pragma unroll
            for (int j = 0; j < 8; ++j) {
                int c = lane + j * 32;
                float v = (Hs[r * Hn + c] - mu) * inv * g1[c] + be1[c];
                Hs[r * Hn + c] = 0.5f * v * (1.f + erff(v * 0.70710678118654752f));
            }
        }
    }
    __syncthreads();

    {
        const float4* Hs4 = (const float4*)Hs;
        const int c2 = tid & 127;
        const int rbase = (tid >> 7) * 16;
        float a2[16];
#pragma unroll
        for (int r = 0; r < 16; ++r) a2[r] = 0.f;
        for (int d = 0; d < Hn; d += 4) {
            float w0 = W2[(d + 0) * Zn + c2];
            float w1 = W2[(d + 1) * Zn + c2];
            float w2 = W2[(d + 2) * Zn + c2];
            float w3 = W2[(d + 3) * Zn + c2];
#pragma unroll
            for (int r = 0; r < 16; ++r) {
                float4 h = Hs4[((rbase + r) * Hn + d) >> 2];
                a2[r] = fmaf(h.x, w0, a2[r]);
                a2[r] = fmaf(h.y, w1, a2[r]);
                a2[r] = fmaf(h.z, w2, a2[r]);
                a2[r] = fmaf(h.w, w3, a2[r]);
            }
        }
        float bb = b2[c2];
#pragma unroll
        for (int r = 0; r < 16; ++r)
            g_enc[(size_t)(row0 + rbase + r) * Zn + c2] = a2[r] + bb;
    }
}

// ---------------- per-row e0 + norms (warp per row) ----------------
__global__ void enorm_kernel()
{
    int gw = (blockIdx.x * 256 + threadIdx.x) >> 5;  // row
    int lane = threadIdx.x & 31;
    const float4 e4 = ((const float4*)(g_enc + (size_t)gw * 128))[lane];
    float e0x = __bfloat162float(__float2bfloat16(e4.x));
    float e0y = __bfloat162float(__float2bfloat16(e4.y));
    float e0z = __bfloat162float(__float2bfloat16(e4.z));
    float e0w = __bfloat162float(__float2bfloat16(e4.w));
    uint2 packed = make_uint2(pack_bf16(e4.x, e4.y), pack_bf16(e4.z, e4.w));
    ((uint2*)(g_e0 + (size_t)gw * 128))[lane] = packed;
    float en2 = e4.x*e4.x + e4.y*e4.y + e4.z*e4.z + e4.w*e4.w;
    float dx = e4.x - e0x, dy = e4.y - e0y, dz = e4.z - e0z, dw = e4.w - e0w;
    float dn2 = dx*dx + dy*dy + dz*dz + dw*dw;
#pragma unroll
    for (int o = 16; o > 0; o >>= 1) {
        en2 += __shfl_xor_sync(0xffffffff, en2, o);
        dn2 += __shfl_xor_sync(0xffffffff, dn2, o);
    }
    if (lane == 0) { g_en2[gw] = en2; g_dn2[gw] = dn2; }
}

// ---------------- codebook: c0, c2h, and max norms (warp per code) ----------------
__global__ void c0split_kernel(const float* __restrict__ C)
{
    int code = (blockIdx.x * 256 + threadIdx.x) >> 5;
    int lane = threadIdx.x & 31;
    const float4 c4 = ((const float4*)(C + (size_t)code * 128))[lane];
    float c0x = __bfloat162float(__float2bfloat16(c4.x));
    float c0y = __bfloat162float(__float2bfloat16(c4.y));
    float c0z = __bfloat162float(__float2bfloat16(c4.z));
    float c0w = __bfloat162float(__float2bfloat16(c4.w));
    ((uint2*)(g_c0 + (size_t)code * 128))[lane] =
        make_uint2(pack_bf16(c4.x, c4.y), pack_bf16(c4.z, c4.w));
    float c2 = c4.x*c4.x + c4.y*c4.y + c4.z*c4.z + c4.w*c4.w;
    float n2 = c0x*c0x + c0y*c0y + c0z*c0z + c0w*c0w;
    float dx = c4.x - c0x, dy = c4.y - c0y, dz = c4.z - c0z, dw = c4.w - c0w;
    float r2 = dx*dx + dy*dy + dz*dz + dw*dw;
#pragma unroll
    for (int o = 16; o > 0; o >>= 1) {
        c2 += __shfl_xor_sync(0xffffffff, c2, o);
        n2 += __shfl_xor_sync(0xffffffff, n2, o);
        r2 += __shfl_xor_sync(0xffffffff, r2, o);
    }
    if (lane == 0) {
        g_c2h[code] = 0.5f * c2;
        atomicMax((int*)&g_Rmax2, __float_as_int(r2));
        atomicMax((int*)&g_Nmax2, __float_as_int(n2));
    }
}

// ---------------- coarse distance: 1-term bf16 mma + per-thread top-3 ----------------
#define LDK2 136
#define SB2_A 0
#define SB2_B (128 * LDK2 * 2)
#define SB2_C2 (2 * 128 * LDK2 * 2)
#define SB2_RED (SB2_C2 + 512)
#define DSM2_TOT (SB2_RED + 128 * 16 * 4)

__global__ __launch_bounds__(512, 1) void dist_coarse_kernel()
{
    extern __shared__ char smem[];
    __nv_bfloat16* As = (__nv_bfloat16*)(smem + SB2_A);
    __nv_bfloat16* Bs = (__nv_bfloat16*)(smem + SB2_B);
    float* c2s = (float*)(smem + SB2_C2);
    float* redsm = (float*)(smem + SB2_RED);

    const int tid  = threadIdx.x;
    const int lane = tid & 31;
    const int wid  = tid >> 5;           // 0..15
    const int warp_m = wid >> 2;         // 0..3 (32-row bands)
    const int warp_n = wid & 3;          // 0..3 (32-code bands)
    const int row0 = blockIdx.x * 128;

    const uint32_t sbA = smem_u32(As);
    const uint32_t sbB = smem_u32(Bs);

    // resident A (128 rows x 128 bf16)
    for (int i = tid; i < 128 * 16; i += 512) {
        int r = i >> 4, u = i & 15;
        uint4 v = ((const uint4*)(g_e0 + (size_t)(row0 + r) * 128))[u];
        *(uint4*)((char*)As + r * (LDK2 * 2) + u * 16) = v;
    }

    uint32_t a_addr[2];
#pragma unroll
    for (int mi = 0; mi < 2; ++mi)
        a_addr[mi] = sbA + ((warp_m * 32 + mi * 16 + (lane & 15)) * LDK2 + (lane >> 4) * 8) * 2;
    uint32_t b_addr[2];
#pragma unroll
    for (int njp = 0; njp < 2; ++njp)
        b_addr[njp] = sbB + ((warp_n * 32 + njp * 16 + (lane & 7) + ((lane >> 4) << 3)) * LDK2
                             + ((lane >> 3) & 1) * 8) * 2;

    // per-thread per-row (4 rows) top-3 of coarse scores
    float v1[4], v2[4], v3[4];
    int   i1[4], i2[4];
#pragma unroll
    for (int r = 0; r < 4; ++r) { v1[r] = v2[r] = v3[r] = -INFINITY; i1[r] = i2[r] = 0; }

    for (int t = 0, kt = 0; t < 128; ++t, kt += 128) {
        __syncthreads();
        for (int i = tid; i < 128 * 16; i += 512) {
            int r = i >> 4, u = i & 15;
            uint4 v = ((const uint4*)(g_c0 + (size_t)(kt + r) * 128))[u];
            *(uint4*)((char*)Bs + r * (LDK2 * 2) + u * 16) = v;
        }
        if (tid < 128) c2s[tid] = g_c2h[kt + tid];
        __syncthreads();

        float acc[2][4][4];
#pragma unroll
        for (int mi = 0; mi < 2; ++mi)
#pragma unroll
            for (int nj = 0; nj < 4; ++nj)
#pragma unroll
                for (int k = 0; k < 4; ++k) acc[mi][nj][k] = 0.f;

#pragma unroll
        for (int s = 0; s < 8; ++s) {
            uint32_t af[2][4], bf[2][4];
#pragma unroll
            for (int mi = 0; mi < 2; ++mi) ldsm_x4(af[mi], a_addr[mi] + s * 32);
#pragma unroll
            for (int njp = 0; njp < 2; ++njp) ldsm_x4(bf[njp], b_addr[njp] + s * 32);
#pragma unroll
            for (int mi = 0; mi < 2; ++mi)
#pragma unroll
                for (int nj = 0; nj < 4; ++nj)
                    mma_bf16(acc[mi][nj], af[mi], bf[nj >> 1] + (nj & 1) * 2);
        }

        // top-3 insertion per row
#pragma unroll
        for (int nj = 0; nj < 4; ++nj) {
            int cbase = warp_n * 32 + nj * 8 + (lane & 3) * 2;
            float c20 = c2s[cbase], c21 = c2s[cbase + 1];
#pragma unroll
            for (int mi = 0; mi < 2; ++mi) {
#pragma unroll
                for (int h = 0; h < 2; ++h) {
                    int ri = mi * 2 + h;
#pragma unroll
                    for (int q = 0; q < 2; ++q) {
                        float v = acc[mi][nj][h * 2 + q] - (q ? c21 : c20);
                        int idx = kt + cbase + q;
                        if (v > v1[ri]) {
                            v3[ri] = v2[ri]; v2[ri] = v1[ri]; i2[ri] = i1[ri];
                            v1[ri] = v; i1[ri] = idx;
                        } else if (v > v2[ri]) {
                            v3[ri] = v2[ri]; v2[ri] = v; i2[ri] = idx;
                        } else if (v > v3[ri]) {
                            v3[ri] = v;
                        }
                    }
                }
            }
        }
    }

    // write candidates + third values; reduce smax
    const int slot = warp_n * 4 + (lane & 3);
#pragma unroll
    for (int ri = 0; ri < 4; ++ri) {
        int mi = ri >> 1, h = ri & 1;
        int lrow = warp_m * 32 + mi * 16 + (lane >> 2) + h * 8;
        size_t row = (size_t)(row0 + lrow);
        g_cand_val[row * 32 + slot * 2]     = v1[ri];
        g_cand_idx[row * 32 + slot * 2]     = i1[ri];
        g_cand_val[row * 32 + slot * 2 + 1] = v2[ri];
        g_cand_idx[row * 32 + slot * 2 + 1] = i2[ri];
        g_third[row * 16 + slot] = v3[ri];
        redsm[lrow * 16 + slot] = v1[ri];
    }
    __syncthreads();
    if (tid < 128) {
        float m = redsm[tid * 16];
#pragma unroll
        for (int w = 1; w < 16; ++w) m = fmaxf(m, redsm[tid * 16 + w]);
        g_smax[row0 + tid] = m;
    }
}

// ---------------- exact rescore of candidates (warp per row) ----------------
__global__ void rescore_kernel(const float* __restrict__ CB)
{
    const int r = blockIdx.x * 4 + (threadIdx.x >> 5);
    const int lane = threadIdx.x & 31;

    float delta = sqrtf(g_en2[r]) * sqrtf(g_Rmax2) + sqrtf(g_dn2[r]) * sqrtf(g_Nmax2);
    float thresh = g_smax[r] - 2.5f * delta - 1e-5f;

    float th = (lane < 16) ? g_third[(size_t)r * 16 + lane] : -INFINITY;
    bool flag = __ballot_sync(0xffffffff, th >= thresh) != 0;

    const float4 e4 = ((const float4*)(g_enc + (size_t)r * 128))[lane];

    float bs = -INFINITY;
    int bi = 0x7fffffff;

    if (!flag) {
        for (int s = 0; s < 32; ++s) {
            float v = g_cand_val[(size_t)r * 32 + s];
            if (v >= thresh) {
                int idx = g_cand_idx[(size_t)r * 32 + s];
                float4 c4 = ((const float4*)(CB + (size_t)idx * 128))[lane];
                float d = e4.x*c4.x + e4.y*c4.y + e4.z*c4.z + e4.w*c4.w;
#pragma unroll
                for (int o = 16; o > 0; o >>= 1) d += __shfl_xor_sync(0xffffffff, d, o);
                float sx = d - g_c2h[idx];
                if (sx > bs || (sx == bs && idx < bi)) { bs = sx; bi = idx; }
            }
        }
    } else {
        // rare safety path: exact scan over all codes
        for (int k = 0; k < Kn; ++k) {
            float4 c4 = ((const float4*)(CB + (size_t)k * 128))[lane];
            float d = e4.x*c4.x + e4.y*c4.y + e4.z*c4.z + e4.w*c4.w;
#pragma unroll
            for (int o = 16; o > 0; o >>= 1) d += __shfl_xor_sync(0xffffffff, d, o);
            float sx = d - g_c2h[k];
            if (sx > bs) { bs = sx; bi = k; }   // ascending k: strict > keeps lowest idx
        }
    }
    if (lane == 0) g_idx[r] = bi;
}

// ---------------- decoder ----------------
__global__ void decoder_kernel(const float* __restrict__ C,
                               const float* __restrict__ W3, const float* __restrict__ b3,
                               const float* __restrict__ g2, const float* __restrict__ be2,
                               const float* __restrict__ W4, const float* __restrict__ b4,
                               const float* __restrict__ X)
{
    extern __shared__ float sm[];
    float* Qs = sm;
    float* Hs = sm + 32 * Zn;
    float* ep = Hs + 32 * Hn;
    const int tid = threadIdx.x;
    const int row0 = blockIdx.x * 32;

    for (int i = tid; i < 32 * 32; i += 256) {
        int r = i >> 5, d4 = i & 31;
        int code = g_idx[row0 + r];
        ((float4*)Qs)[r * 32 + d4] = ((const float4*)C)[(size_t)code * 32 + d4];
    }
    __syncthreads();

    {
        const float4* Qs4 = (const float4*)Qs;
        float acc[32];
#pragma unroll
        for (int r = 0; r < 32; ++r) acc[r] = 0.f;
        const int col = tid;
        for (int d = 0; d < Zn; d += 4) {
            float w0 = W3[(d + 0) * Hn + col];
            float w1 = W3[(d + 1) * Hn + col];
            float w2 = W3[(d + 2) * Hn + col];
            float w3 = W3[(d + 3) * Hn + col];
#pragma unroll
            for (int r = 0; r < 32; ++r) {
                float4 q = Qs4[(r * Zn + d) >> 2];
                acc[r] = fmaf(q.x, w0, acc[r]);
                acc[r] = fmaf(q.y, w1, acc[r]);
                acc[r] = fmaf(q.z, w2, acc[r]);
                acc[r] = fmaf(q.w, w3, acc[r]);
            }
        }
        float bb = b3[col];
#pragma unroll
        for (int r = 0; r < 32; ++r) Hs[r * Hn + col] = acc[r] + bb;
    }
    __syncthreads();

    {
        const int warp = tid >> 5, lane = tid & 31;
        for (int rr = 0; rr < 4; ++rr) {
            int r = warp + rr * 8;
            float s = 0.f, s2 = 0.f;
#pragma unroll
            for (int j = 0; j < 8; ++j) {
                float v = Hs[r * Hn + lane + j * 32];
                s += v; s2 += v * v;
            }
#pragma unroll
            for (int o = 16; o > 0; o >>= 1) {
                s  += __shfl_xor_sync(0xffffffff, s,  o);
                s2 += __shfl_xor_sync(0xffffffff, s2, o);
            }
            float mu  = s * (1.f / Hn);
            float var = s2 * (1.f / Hn) - mu * mu;
            float inv = rsqrtf(var + 1e-5f);
#pragma unroll
            for (int j = 0; j < 8; ++j) {
                int c = lane + j * 32;
                float v = (Hs[r * Hn + c] - mu) * inv * g2[c] + be2[c];
                Hs[r * Hn + c] = 0.5f * v * (1.f + erff(v * 0.70710678118654752f));
            }
        }
    }
    __syncthreads();

    float aA[32], aB[32];
#pragma unroll
    for (int r = 0; r < 32; ++r) { aA[r] = 0.f; aB[r] = 0.f; }
    {
        const float4* Hs4 = (const float4*)Hs;
        for (int d = 0; d < Hn; d += 4) {
            float wa0 = W4[(d + 0) * Dn + tid];
            float wa1 = W4[(d + 1) * Dn + tid];
            float wa2 = W4[(d + 2) * Dn + tid];
            float wa3 = W4[(d + 3) * Dn + tid];
            float wb0 = W4[(d + 0) * Dn + tid + 256];
            float wb1 = W4[(d + 1) * Dn + tid + 256];
            float wb2 = W4[(d + 2) * Dn + tid + 256];
            float wb3 = W4[(d + 3) * Dn + tid + 256];
#pragma unroll
            for (int r = 0; r < 32; ++r) {
                float4 h = Hs4[(r * Hn + d) >> 2];
                aA[r] = fmaf(h.x, wa0, aA[r]);
                aA[r] = fmaf(h.y, wa1, aA[r]);
                aA[r] = fmaf(h.z, wa2, aA[r]);
                aA[r] = fmaf(h.w, wa3, aA[r]);
                aB[r] = fmaf(h.x, wb0, aB[r]);
                aB[r] = fmaf(h.y, wb1, aB[r]);
                aB[r] = fmaf(h.z, wb2, aB[r]);
                aB[r] = fmaf(h.w, wb3, aB[r]);
            }
        }
    }

    {
        const int warp = tid >> 5, lane = tid & 31;
        float b4a = b4[tid], b4b = b4[tid + 256];
        for (int r = 0; r < 32; ++r) {
            float f1 = X[(size_t)(row0 + r) * Dn + tid];
            float f2 = X[(size_t)(row0 + r) * Dn + tid + 256];
            float d1 = aA[r] + b4a - f1;
            float d2 = aB[r] + b4b - f2;
            float e = d1 * d1 + d2 * d2;
#pragma unroll
            for (int o = 16; o > 0; o >>= 1) e += __shfl_xor_sync(0xffffffff, e, o);
            if (lane == 0) ep[r * 8 + warp] = e;
        }
        __syncthreads();
        if (tid < 32) {
            float s = 0.f;
#pragma unroll
            for (int w = 0; w < 8; ++w) s += ep[tid * 8 + w];
            g_err[row0 + tid] = s * (1.f / Dn);
        }
    }
}

// ---------------- global mean ----------------
__global__ void reduce_kernel()
{
    __shared__ float s[256];
    int tid = threadIdx.x;
    float a = 0.f;
    for (int i = tid; i < Bn; i += 256) a += g_err[i];
    s[tid] = a;
    __syncthreads();
    for (int o = 128; o > 0; o >>= 1) {
        if (tid < o) s[tid] += s[tid + o];
        __syncthreads();
    }
    if (tid == 0) g_sum = s[0];
}

// ---------------- MDL + output ----------------
__global__ void final_kernel(float* __restrict__ out)
{
    int i = blockIdx.x * 256 + threadIdx.x;
    float scale = g_sum * (1.f / Bn) + 1e-8f;
    float err = g_err[i];
    float eb = (fabsf(err) / scale + logf(2.f * scale)) * 1.4426950408889634f;
    float tb = 14.f + eb;
    out[i]          = err;
    out[Bn + i]     = (Dn * 32.f) / tb;
    out[2 * Bn + i] = tb;
    out[3 * Bn + i] = (float)g_idx[i];
}

// ---------------- launch ----------------
extern "C" void kernel_launch(void* const* d_in, const int* in_sizes, int n_in,
                              void* d_out, int out_size)
{
    const float* X   = (const float*)d_in[0];
    const float* W1  = (const float*)d_in[1];
    const float* b1  = (const float*)d_in[2];
    const float* g1  = (const float*)d_in[3];
    const float* be1 = (const float*)d_in[4];
    const float* W2  = (const float*)d_in[5];
    const float* b2  = (const float*)d_in[6];
    const float* CB  = (const float*)d_in[7];
    const float* W3  = (const float*)d_in[8];
    const float* b3  = (const float*)d_in[9];
    const float* g2  = (const float*)d_in[10];
    const float* be2 = (const float*)d_in[11];
    const float* W4  = (const float*)d_in[12];
    const float* b4  = (const float*)d_in[13];
    float* out = (float*)d_out;

    cudaFuncSetAttribute(encoder_kernel,     cudaFuncAttributeMaxDynamicSharedMemorySize, 98304);
    cudaFuncSetAttribute(dist_coarse_kernel, cudaFuncAttributeMaxDynamicSharedMemorySize, DSM2_TOT);
    cudaFuncSetAttribute(decoder_kernel,     cudaFuncAttributeMaxDynamicSharedMemorySize, 50176);

    c0split_kernel<<<Kn / 8, 256>>>(CB);
    encoder_kernel<<<Bn / 32, 256, 98304>>>(X, W1, b1, g1, be1, W2, b2);
    enorm_kernel<<<Bn / 8, 256>>>();
    dist_coarse_kernel<<<Bn / 128, 512, DSM2_TOT>>>();
    rescore_kernel<<<Bn / 4, 128>>>(CB);
    decoder_kernel<<<Bn / 32, 256, 50176>>>(CB, W3, b3, g2, be2, W4, b4, X);
    reduce_kernel<<<1, 256>>>();
    final_kernel<<<Bn / 256, 256>>>(out);
}

// round 6
// speedup vs baseline: 2.7241x; 2.6141x over previous
#include <cuda_runtime.h>
#include <cuda_bf16.h>
#include <math.h>
#include <stdint.h>

#define Bn 16384
#define Dn 512
#define Kn 16384
#define Hn 256
#define Zn 128

// ---------------- scratch ----------------
__device__ __align__(16) float g_enc[(size_t)Bn * Zn];          // encoded fp32
__device__ __align__(16) __nv_bfloat16 g_e0[(size_t)Bn * Zn];   // bf16(encoded)
__device__ __align__(16) __nv_bfloat16 g_c0[(size_t)Kn * Zn];   // bf16(codebook)
__device__ float g_negc2[Kn];        // -0.5*||c||^2 exact
__device__ float g_en2[Bn];          // ||e||^2
__device__ float g_dn2[Bn];          // ||e-e0||^2
__device__ float g_Rmax2;            // max_k ||c-c0||^2
__device__ float g_Nmax2;            // max_k ||c0||^2
__device__ float g_smax[Bn];         // per-row max coarse score
__device__ float g_cand_val[(size_t)Bn * 48];
__device__ int   g_cand_idx[(size_t)Bn * 48];
__device__ float g_fourth[(size_t)Bn * 16];
__device__ int   g_idx[Bn];
__device__ float g_err[Bn];
__device__ float g_sum;

// ---------------- helpers ----------------
__device__ __forceinline__ uint32_t smem_u32(const void* p) {
    uint32_t a;
    asm("{ .reg .u64 t; cvta.to.shared.u64 t, %1; cvt.u32.u64 %0, t; }" : "=r"(a) : "l"(p));
    return a;
}
__device__ __forceinline__ void ldsm_x4(uint32_t r[4], uint32_t addr) {
    asm volatile("ldmatrix.sync.aligned.m8n8.x4.shared.b16 {%0,%1,%2,%3}, [%4];"
        : "=r"(r[0]), "=r"(r[1]), "=r"(r[2]), "=r"(r[3]) : "r"(addr));
}
__device__ __forceinline__ void mma_bf16(float d[4], const uint32_t a[4], const uint32_t b[2]) {
    asm volatile("mma.sync.aligned.m16n8k16.row.col.f32.bf16.bf16.f32 "
        "{%0,%1,%2,%3}, {%4,%5,%6,%7}, {%8,%9}, {%0,%1,%2,%3};"
        : "+f"(d[0]), "+f"(d[1]), "+f"(d[2]), "+f"(d[3])
        : "r"(a[0]), "r"(a[1]), "r"(a[2]), "r"(a[3]), "r"(b[0]), "r"(b[1]));
}
__device__ __forceinline__ uint32_t pack_bf16(float a, float b) {
    __nv_bfloat162 t = __floats2bfloat162_rn(a, b);
    return *(uint32_t*)&t;
}
__device__ __forceinline__ void cpasync16(uint32_t saddr, const void* g) {
    asm volatile("cp.async.cg.shared.global [%0], [%1], 16;" :: "r"(saddr), "l"(g));
}
#define CP_COMMIT() asm volatile("cp.async.commit_group;" ::: "memory")
#define CP_WAIT1()  asm volatile("cp.async.wait_group 1;" ::: "memory")
#define CP_WAIT0()  asm volatile("cp.async.wait_group 0;" ::: "memory")

// ---------------- encoder: X@W1+b1 -> LN -> GELU -> @W2+b2 (fp32 out) ----------------
__global__ void encoder_kernel(const float* __restrict__ X,
                               const float* __restrict__ W1, const float* __restrict__ b1,
                               const float* __restrict__ g1, const float* __restrict__ be1,
                               const float* __restrict__ W2, const float* __restrict__ b2)
{
    extern __shared__ float sm[];
    float* Xs = sm;
    float* Hs = sm + 32 * Dn;
    const int tid = threadIdx.x;
    const int row0 = blockIdx.x * 32;

    {
        const float4* Xg = (const float4*)(X + (size_t)row0 * Dn);
        float4* Xs4 = (float4*)Xs;
        for (int i = tid; i < 32 * Dn / 4; i += 256) Xs4[i] = Xg[i];
    }
    __syncthreads();

    const float4* Xs4 = (const float4*)Xs;
    float acc[32];
#pragma unroll
    for (int r = 0; r < 32; ++r) acc[r] = 0.f;
    const int col = tid;
    for (int d = 0; d < Dn; d += 4) {
        float w0 = W1[(d + 0) * Hn + col];
        float w1 = W1[(d + 1) * Hn + col];
        float w2 = W1[(d + 2) * Hn + col];
        float w3 = W1[(d + 3) * Hn + col];
#pragma unroll
        for (int r = 0; r < 32; ++r) {
            float4 x = Xs4[(r * Dn + d) >> 2];
            acc[r] = fmaf(x.x, w0, acc[r]);
            acc[r] = fmaf(x.y, w1, acc[r]);
            acc[r] = fmaf(x.z, w2, acc[r]);
            acc[r] = fmaf(x.w, w3, acc[r]);
        }
    }
    {
        float bb = b1[col];
#pragma unroll
        for (int r = 0; r < 32; ++r) Hs[r * Hn + col] = acc[r] + bb;
    }
    __syncthreads();

    {
        const int warp = tid >> 5, lane = tid & 31;
        for (int rr = 0; rr < 4; ++rr) {
            int r = warp + rr * 8;
            float s = 0.f, s2 = 0.f;
#pragma unroll
            for (int j = 0; j < 8; ++j) {
                float v = Hs[r * Hn + lane + j * 32];
                s += v; s2 += v * v;
            }
#pragma unroll
            for (int o = 16; o > 0; o >>= 1) {
                s  += __shfl_xor_sync(0xffffffff, s,  o);
                s2 += __shfl_xor_sync(0xffffffff, s2, o);
            }
            float mu  = s * (1.f / Hn);
            float var = s2 * (1.f / Hn) - mu * mu;
            float inv = rsqrtf(var + 1e-5f);
#pragma unroll
            for (int j = 0; j < 8; ++j) {
                int c = lane + j * 32;
                float v = (Hs[r * Hn + c] - mu) * inv * g1[c] + be1[c];
                Hs[r * Hn + c] = 0.5f * v * (1.f + erff(v * 0.70710678118654752f));
            }
        }
    }
    __syncthreads();

    {
        const float4* Hs4 = (const float4*)Hs;
        const int c2 = tid & 127;
        const int rbase = (tid >> 7) * 16;
        float a2[16];
#pragma unroll
        for (int r = 0; r < 16; ++r) a2[r] = 0.f;
        for (int d = 0; d < Hn; d += 4) {
            float w0 = W2[(d + 0) * Zn + c2];
            float w1 = W2[(d + 1) * Zn + c2];
            float w2 = W2[(d + 2) * Zn + c2];
            float w3 = W2[(d + 3) * Zn + c2];
#pragma unroll
            for (int r = 0; r < 16; ++r) {
                float4 h = Hs4[((rbase + r) * Hn + d) >> 2];
                a2[r] = fmaf(h.x, w0, a2[r]);
                a2[r] = fmaf(h.y, w1, a2[r]);
                a2[r] = fmaf(h.z, w2, a2[r]);
                a2[r] = fmaf(h.w, w3, a2[r]);
            }
        }
        float bb = b2[c2];
#pragma unroll
        for (int r = 0; r < 16; ++r)
            g_enc[(size_t)(row0 + rbase + r) * Zn + c2] = a2[r] + bb;
    }
}

// ---------------- per-row e0 + norms (warp per row) ----------------
__global__ void enorm_kernel()
{
    int gw = (blockIdx.x * 256 + threadIdx.x) >> 5;
    int lane = threadIdx.x & 31;
    const float4 e4 = ((const float4*)(g_enc + (size_t)gw * 128))[lane];
    float e0x = __bfloat162float(__float2bfloat16(e4.x));
    float e0y = __bfloat162float(__float2bfloat16(e4.y));
    float e0z = __bfloat162float(__float2bfloat16(e4.z));
    float e0w = __bfloat162float(__float2bfloat16(e4.w));
    ((uint2*)(g_e0 + (size_t)gw * 128))[lane] =
        make_uint2(pack_bf16(e4.x, e4.y), pack_bf16(e4.z, e4.w));
    float en2 = e4.x*e4.x + e4.y*e4.y + e4.z*e4.z + e4.w*e4.w;
    float dx = e4.x - e0x, dy = e4.y - e0y, dz = e4.z - e0z, dw = e4.w - e0w;
    float dn2 = dx*dx + dy*dy + dz*dz + dw*dw;
#pragma unroll
    for (int o = 16; o > 0; o >>= 1) {
        en2 += __shfl_xor_sync(0xffffffff, en2, o);
        dn2 += __shfl_xor_sync(0xffffffff, dn2, o);
    }
    if (lane == 0) { g_en2[gw] = en2; g_dn2[gw] = dn2; }
}

// ---------------- codebook: c0, -0.5||c||^2, max norms ----------------
__global__ void c0split_kernel(const float* __restrict__ C)
{
    int code = (blockIdx.x * 256 + threadIdx.x) >> 5;
    int lane = threadIdx.x & 31;
    const float4 c4 = ((const float4*)(C + (size_t)code * 128))[lane];
    float c0x = __bfloat162float(__float2bfloat16(c4.x));
    float c0y = __bfloat162float(__float2bfloat16(c4.y));
    float c0z = __bfloat162float(__float2bfloat16(c4.z));
    float c0w = __bfloat162float(__float2bfloat16(c4.w));
    ((uint2*)(g_c0 + (size_t)code * 128))[lane] =
        make_uint2(pack_bf16(c4.x, c4.y), pack_bf16(c4.z, c4.w));
    float c2 = c4.x*c4.x + c4.y*c4.y + c4.z*c4.z + c4.w*c4.w;
    float n2 = c0x*c0x + c0y*c0y + c0z*c0z + c0w*c0w;
    float dx = c4.x - c0x, dy = c4.y - c0y, dz = c4.z - c0z, dw = c4.w - c0w;
    float r2 = dx*dx + dy*dy + dz*dz + dw*dw;
#pragma unroll
    for (int o = 16; o > 0; o >>= 1) {
        c2 += __shfl_xor_sync(0xffffffff, c2, o);
        n2 += __shfl_xor_sync(0xffffffff, n2, o);
        r2 += __shfl_xor_sync(0xffffffff, r2, o);
    }
    if (lane == 0) {
        g_negc2[code] = -0.5f * c2;
        atomicMax((int*)&g_Rmax2, __float_as_int(r2));
        atomicMax((int*)&g_Nmax2, __float_as_int(n2));
    }
}

// ---------------- coarse distance: 1-term bf16 mma, cp.async dbuf, top-4 ----------------
#define LDK2 136
#define TILE_BYTES (128 * LDK2 * 2)     // 34816
#define SB_A 0
#define SB_B0 TILE_BYTES
#define SB_RED (TILE_BYTES * 3)
#define DSM2_TOT (SB_RED + 128 * 16 * 4)

__global__ __launch_bounds__(512, 1) void dist_coarse_kernel()
{
    extern __shared__ char smem[];
    float* redsm = (float*)(smem + SB_RED);

    const int tid  = threadIdx.x;
    const int lane = tid & 31;
    const int wid  = tid >> 5;           // 0..15
    const int warp_m = wid >> 2;         // 0..3
    const int warp_n = wid & 3;          // 0..3
    const int row0 = blockIdx.x * 128;

    const uint32_t sbA  = smem_u32(smem) + SB_A;
    const uint32_t sbB0 = smem_u32(smem) + SB_B0;

    // prologue: async load resident A (group), then B tile 0 (group)
    for (int i = tid; i < 2048; i += 512) {
        int r = i >> 4, u = i & 15;
        cpasync16(sbA + r * (LDK2 * 2) + u * 16,
                  g_e0 + (size_t)(row0 + r) * 128 + u * 8);
    }
    CP_COMMIT();
    for (int i = tid; i < 2048; i += 512) {
        int r = i >> 4, u = i & 15;
        cpasync16(sbB0 + r * (LDK2 * 2) + u * 16,
                  g_c0 + (size_t)r * 128 + u * 8);
    }
    CP_COMMIT();

    uint32_t a_addr[2];
#pragma unroll
    for (int mi = 0; mi < 2; ++mi)
        a_addr[mi] = sbA + ((warp_m * 32 + mi * 16 + (lane & 15)) * LDK2 + (lane >> 4) * 8) * 2;
    uint32_t b_addr[2];
#pragma unroll
    for (int njp = 0; njp < 2; ++njp)
        b_addr[njp] = sbB0 + ((warp_n * 32 + njp * 16 + (lane & 7) + ((lane >> 4) << 3)) * LDK2
                              + ((lane >> 3) & 1) * 8) * 2;

    // top-4 values, top-3 idx, per row (4 rows per thread)
    float v1[4], v2[4], v3[4], v4[4];
    int   i1[4], i2[4], i3[4];
#pragma unroll
    for (int r = 0; r < 4; ++r) {
        v1[r] = v2[r] = v3[r] = v4[r] = -INFINITY;
        i1[r] = i2[r] = i3[r] = 0;
    }

    const int cq = (lane & 3) * 2;       // code sub-offset within nj band

    for (int t = 0, kt = 0; t < 128; ++t, kt += 128) {
        const uint32_t bufo = (uint32_t)(t & 1) * TILE_BYTES;
        if (t < 127) {
            uint32_t sb = sbB0 + ((t + 1) & 1) * TILE_BYTES;
            const __nv_bfloat16* src = g_c0 + (size_t)(kt + 128) * 128;
            for (int i = tid; i < 2048; i += 512) {
                int r = i >> 4, u = i & 15;
                cpasync16(sb + r * (LDK2 * 2) + u * 16, src + (size_t)r * 128 + u * 8);
            }
            CP_COMMIT();
            CP_WAIT1();
        } else {
            CP_WAIT0();
        }
        __syncthreads();

        // prefetch -0.5||c||^2 for this thread's 8 codes (hidden under MMA)
        float nc[8];
#pragma unroll
        for (int nj = 0; nj < 4; ++nj) {
            nc[nj * 2]     = g_negc2[kt + warp_n * 32 + nj * 8 + cq];
            nc[nj * 2 + 1] = g_negc2[kt + warp_n * 32 + nj * 8 + cq + 1];
        }

        float acc[2][4][4];
#pragma unroll
        for (int mi = 0; mi < 2; ++mi)
#pragma unroll
            for (int nj = 0; nj < 4; ++nj)
#pragma unroll
                for (int k = 0; k < 4; ++k) acc[mi][nj][k] = 0.f;

#pragma unroll
        for (int s = 0; s < 8; ++s) {
            uint32_t af[2][4], bf[2][4];
#pragma unroll
            for (int mi = 0; mi < 2; ++mi) ldsm_x4(af[mi], a_addr[mi] + s * 32);
#pragma unroll
            for (int njp = 0; njp < 2; ++njp) ldsm_x4(bf[njp], b_addr[njp] + bufo + s * 32);
#pragma unroll
            for (int mi = 0; mi < 2; ++mi)
#pragma unroll
                for (int nj = 0; nj < 4; ++nj)
                    mma_bf16(acc[mi][nj], af[mi], bf[nj >> 1] + (nj & 1) * 2);
        }

        // epilogue: max-of-8 quick reject, then rare insert
#pragma unroll
        for (int mi = 0; mi < 2; ++mi) {
#pragma unroll
            for (int h = 0; h < 2; ++h) {
                const int ri = mi * 2 + h;
                float s0 = acc[mi][0][h * 2]     + nc[0];
                float s1 = acc[mi][0][h * 2 + 1] + nc[1];
                float s2 = acc[mi][1][h * 2]     + nc[2];
                float s3 = acc[mi][1][h * 2 + 1] + nc[3];
                float s4 = acc[mi][2][h * 2]     + nc[4];
                float s5 = acc[mi][2][h * 2 + 1] + nc[5];
                float s6 = acc[mi][3][h * 2]     + nc[6];
                float s7 = acc[mi][3][h * 2 + 1] + nc[7];
                float m8 = fmaxf(fmaxf(fmaxf(s0, s1), fmaxf(s2, s3)),
                                 fmaxf(fmaxf(s4, s5), fmaxf(s6, s7)));
                if (m8 > v4[ri]) {
                    float sv[8] = {s0, s1, s2, s3, s4, s5, s6, s7};
#pragma unroll
                    for (int j = 0; j < 8; ++j) {
                        float v = sv[j];
                        if (v > v4[ri]) {
                            int idx = kt + warp_n * 32 + (j >> 1) * 8 + cq + (j & 1);
                            if (v > v1[ri]) {
                                v4[ri] = v3[ri]; v3[ri] = v2[ri]; i3[ri] = i2[ri];
                                v2[ri] = v1[ri]; i2[ri] = i1[ri];
                                v1[ri] = v; i1[ri] = idx;
                            } else if (v > v2[ri]) {
                                v4[ri] = v3[ri]; v3[ri] = v2[ri]; i3[ri] = i2[ri];
                                v2[ri] = v; i2[ri] = idx;
                            } else if (v > v3[ri]) {
                                v4[ri] = v3[ri]; v3[ri] = v; i3[ri] = idx;
                            } else {
                                v4[ri] = v;
                            }
                        }
                    }
                }
            }
        }
        __syncthreads();   // all reads of buf done before t+1 prefetches into it
    }

    // write candidates + v4; reduce smax
    const int slot = warp_n * 4 + (lane & 3);
#pragma unroll
    for (int ri = 0; ri < 4; ++ri) {
        int mi = ri >> 1, h = ri & 1;
        int lrow = warp_m * 32 + mi * 16 + (lane >> 2) + h * 8;
        size_t row = (size_t)(row0 + lrow);
        g_cand_val[row * 48 + slot * 3]     = v1[ri];
        g_cand_idx[row * 48 + slot * 3]     = i1[ri];
        g_cand_val[row * 48 + slot * 3 + 1] = v2[ri];
        g_cand_idx[row * 48 + slot * 3 + 1] = i2[ri];
        g_cand_val[row * 48 + slot * 3 + 2] = v3[ri];
        g_cand_idx[row * 48 + slot * 3 + 2] = i3[ri];
        g_fourth[row * 16 + slot] = v4[ri];
        redsm[lrow * 16 + slot] = v1[ri];
    }
    __syncthreads();
    if (tid < 128) {
        float m = redsm[tid * 16];
#pragma unroll
        for (int w = 1; w < 16; ++w) m = fmaxf(m, redsm[tid * 16 + w]);
        g_smax[row0 + tid] = m;
    }
}

// ---------------- exact rescore of candidates (warp per row) ----------------
__global__ void rescore_kernel(const float* __restrict__ CB)
{
    const int r = blockIdx.x * 4 + (threadIdx.x >> 5);
    const int lane = threadIdx.x & 31;

    float delta = sqrtf(g_en2[r]) * sqrtf(g_Rmax2) + sqrtf(g_dn2[r]) * sqrtf(g_Nmax2);
    float thresh = g_smax[r] - 1.05f * delta - 1e-4f;

    float th = (lane < 16) ? g_fourth[(size_t)r * 16 + lane] : -INFINITY;
    bool flag = __ballot_sync(0xffffffff, th >= thresh) != 0;

    const float4 e4 = ((const float4*)(g_enc + (size_t)r * 128))[lane];

    float bs = -INFINITY;
    int bi = 0x7fffffff;

    if (!flag) {
        for (int s = 0; s < 48; ++s) {
            float v = g_cand_val[(size_t)r * 48 + s];
            if (v >= thresh) {
                int idx = g_cand_idx[(size_t)r * 48 + s];
                float4 c4 = ((const float4*)(CB + (size_t)idx * 128))[lane];
                float d = e4.x*c4.x + e4.y*c4.y + e4.z*c4.z + e4.w*c4.w;
#pragma unroll
                for (int o = 16; o > 0; o >>= 1) d += __shfl_xor_sync(0xffffffff, d, o);
                float sx = d + g_negc2[idx];
                if (sx > bs || (sx == bs && idx < bi)) { bs = sx; bi = idx; }
            }
        }
    } else {
        // safety path (statistically never): exact scan over all codes
        for (int k = 0; k < Kn; ++k) {
            float4 c4 = ((const float4*)(CB + (size_t)k * 128))[lane];
            float d = e4.x*c4.x + e4.y*c4.y + e4.z*c4.z + e4.w*c4.w;
#pragma unroll
            for (int o = 16; o > 0; o >>= 1) d += __shfl_xor_sync(0xffffffff, d, o);
            float sx = d + g_negc2[k];
            if (sx > bs) { bs = sx; bi = k; }
        }
    }
    if (lane == 0) g_idx[r] = bi;
}

// ---------------- decoder ----------------
__global__ void decoder_kernel(const float* __restrict__ C,
                               const float* __restrict__ W3, const float* __restrict__ b3,
                               const float* __restrict__ g2, const float* __restrict__ be2,
                               const float* __restrict__ W4, const float* __restrict__ b4,
                               const float* __restrict__ X)
{
    extern __shared__ float sm[];
    float* Qs = sm;
    float* Hs = sm + 32 * Zn;
    float* ep = Hs + 32 * Hn;
    const int tid = threadIdx.x;
    const int row0 = blockIdx.x * 32;

    for (int i = tid; i < 32 * 32; i += 256) {
        int r = i >> 5, d4 = i & 31;
        int code = g_idx[row0 + r];
        ((float4*)Qs)[r * 32 + d4] = ((const float4*)C)[(size_t)code * 32 + d4];
    }
    __syncthreads();

    {
        const float4* Qs4 = (const float4*)Qs;
        float acc[32];
#pragma unroll
        for (int r = 0; r < 32; ++r) acc[r] = 0.f;
        const int col = tid;
        for (int d = 0; d < Zn; d += 4) {
            float w0 = W3[(d + 0) * Hn + col];
            float w1 = W3[(d + 1) * Hn + col];
            float w2 = W3[(d + 2) * Hn + col];
            float w3 = W3[(d + 3) * Hn + col];
#pragma unroll
            for (int r = 0; r < 32; ++r) {
                float4 q = Qs4[(r * Zn + d) >> 2];
                acc[r] = fmaf(q.x, w0, acc[r]);
                acc[r] = fmaf(q.y, w1, acc[r]);
                acc[r] = fmaf(q.z, w2, acc[r]);
                acc[r] = fmaf(q.w, w3, acc[r]);
            }
        }
        float bb = b3[col];
#pragma unroll
        for (int r = 0; r < 32; ++r) Hs[r * Hn + col] = acc[r] + bb;
    }
    __syncthreads();

    {
        const int warp = tid >> 5, lane = tid & 31;
        for (int rr = 0; rr < 4; ++rr) {
            int r = warp + rr * 8;
            float s = 0.f, s2 = 0.f;
#pragma unroll
            for (int j = 0; j < 8; ++j) {
                float v = Hs[r * Hn + lane + j * 32];
                s += v; s2 += v * v;
            }
#pragma unroll
            for (int o = 16; o > 0; o >>= 1) {
                s  += __shfl_xor_sync(0xffffffff, s,  o);
                s2 += __shfl_xor_sync(0xffffffff, s2, o);
            }
            float mu  = s * (1.f / Hn);
            float var = s2 * (1.f / Hn) - mu * mu;
            float inv = rsqrtf(var + 1e-5f);
#pragma unroll
            for (int j = 0; j < 8; ++j) {
                int c = lane + j * 32;
                float v = (Hs[r * Hn + c] - mu) * inv * g2[c] + be2[c];
                Hs[r * Hn + c] = 0.5f * v * (1.f + erff(v * 0.70710678118654752f));
            }
        }
    }
    __syncthreads();

    float aA[32], aB[32];
#pragma unroll
    for (int r = 0; r < 32; ++r) { aA[r] = 0.f; aB[r] = 0.f; }
    {
        const float4* Hs4 = (const float4*)Hs;
        for (int d = 0; d < Hn; d += 4) {
            float wa0 = W4[(d + 0) * Dn + tid];
            float wa1 = W4[(d + 1) * Dn + tid];
            float wa2 = W4[(d + 2) * Dn + tid];
            float wa3 = W4[(d + 3) * Dn + tid];
            float wb0 = W4[(d + 0) * Dn + tid + 256];
            float wb1 = W4[(d + 1) * Dn + tid + 256];
            float wb2 = W4[(d + 2) * Dn + tid + 256];
            float wb3 = W4[(d + 3) * Dn + tid + 256];
#pragma unroll
            for (int r = 0; r < 32; ++r) {
                float4 h = Hs4[(r * Hn + d) >> 2];
                aA[r] = fmaf(h.x, wa0, aA[r]);
                aA[r] = fmaf(h.y, wa1, aA[r]);
                aA[r] = fmaf(h.z, wa2, aA[r]);
                aA[r] = fmaf(h.w, wa3, aA[r]);
                aB[r] = fmaf(h.x, wb0, aB[r]);
                aB[r] = fmaf(h.y, wb1, aB[r]);
                aB[r] = fmaf(h.z, wb2, aB[r]);
                aB[r] = fmaf(h.w, wb3, aB[r]);
            }
        }
    }

    {
        const int warp = tid >> 5, lane = tid & 31;
        float b4a = b4[tid], b4b = b4[tid + 256];
        for (int r = 0; r < 32; ++r) {
            float f1 = X[(size_t)(row0 + r) * Dn + tid];
            float f2 = X[(size_t)(row0 + r) * Dn + tid + 256];
            float d1 = aA[r] + b4a - f1;
            float d2 = aB[r] + b4b - f2;
            float e = d1 * d1 + d2 * d2;
#pragma unroll
            for (int o = 16; o > 0; o >>= 1) e += __shfl_xor_sync(0xffffffff, e, o);
            if (lane == 0) ep[r * 8 + warp] = e;
        }
        __syncthreads();
        if (tid < 32) {
            float s = 0.f;
#pragma unroll
            for (int w = 0; w < 8; ++w) s += ep[tid * 8 + w];
            g_err[row0 + tid] = s * (1.f / Dn);
        }
    }
}

// ---------------- global mean ----------------
__global__ void reduce_kernel()
{
    __shared__ float s[256];
    int tid = threadIdx.x;
    float a = 0.f;
    for (int i = tid; i < Bn; i += 256) a += g_err[i];
    s[tid] = a;
    __syncthreads();
    for (int o = 128; o > 0; o >>= 1) {
        if (tid < o) s[tid] += s[tid + o];
        __syncthreads();
    }
    if (tid == 0) g_sum = s[0];
}

// ---------------- MDL + output ----------------
__global__ void final_kernel(float* __restrict__ out)
{
    int i = blockIdx.x * 256 + threadIdx.x;
    float scale = g_sum * (1.f / Bn) + 1e-8f;
    float err = g_err[i];
    float eb = (fabsf(err) / scale + logf(2.f * scale)) * 1.4426950408889634f;
    float tb = 14.f + eb;
    out[i]          = err;
    out[Bn + i]     = (Dn * 32.f) / tb;
    out[2 * Bn + i] = tb;
    out[3 * Bn + i] = (float)g_idx[i];
}

// ---------------- launch ----------------
extern "C" void kernel_launch(void* const* d_in, const int* in_sizes, int n_in,
                              void* d_out, int out_size)
{
    const float* X   = (const float*)d_in[0];
    const float* W1  = (const float*)d_in[1];
    const float* b1  = (const float*)d_in[2];
    const float* g1  = (const float*)d_in[3];
    const float* be1 = (const float*)d_in[4];
    const float* W2  = (const float*)d_in[5];
    const float* b2  = (const float*)d_in[6];
    const float* CB  = (const float*)d_in[7];
    const float* W3  = (const float*)d_in[8];
    const float* b3  = (const float*)d_in[9];
    const float* g2  = (const float*)d_in[10];
    const float* be2 = (const float*)d_in[11];
    const float* W4  = (const float*)d_in[12];
    const float* b4  = (const float*)d_in[13];
    float* out = (float*)d_out;

    cudaFuncSetAttribute(encoder_kernel,     cudaFuncAttributeMaxDynamicSharedMemorySize, 98304);
    cudaFuncSetAttribute(dist_coarse_kernel, cudaFuncAttributeMaxDynamicSharedMemorySize, DSM2_TOT);
    cudaFuncSetAttribute(decoder_kernel,     cudaFuncAttributeMaxDynamicSharedMemorySize, 50176);

    c0split_kernel<<<Kn / 8, 256>>>(CB);
    encoder_kernel<<<Bn / 32, 256, 98304>>>(X, W1, b1, g1, be1, W2, b2);
    enorm_kernel<<<Bn / 8, 256>>>();
    dist_coarse_kernel<<<Bn / 128, 512, DSM2_TOT>>>();
    rescore_kernel<<<Bn / 4, 128>>>(CB);
    decoder_kernel<<<Bn / 32, 256, 50176>>>(CB, W3, b3, g2, be2, W4, b4, X);
    reduce_kernel<<<1, 256>>>();
    final_kernel<<<Bn / 256, 256>>>(out);
}

// round 7
// speedup vs baseline: 2.9430x; 1.0803x over previous
#include <cuda_runtime.h>
#include <cuda_bf16.h>
#include <math.h>
#include <stdint.h>

#define Bn 16384
#define Dn 512
#define Kn 16384
#define Hn 256
#define Zn 128

// ---------------- scratch ----------------
__device__ __align__(16) float g_enc[(size_t)Bn * Zn];          // encoded fp32
__device__ __align__(16) __nv_bfloat16 g_e0[(size_t)Bn * Zn];   // bf16(encoded)
__device__ __align__(16) __nv_bfloat16 g_c0[(size_t)Kn * Zn];   // bf16(codebook)
__device__ float g_negc2[Kn];        // -0.5*||c||^2 exact
__device__ float g_en2[Bn];          // ||e||^2
__device__ float g_dn2[Bn];          // ||e-e0||^2
__device__ float g_Rmax2;            // max_k ||c-c0||^2
__device__ float g_Nmax2;            // max_k ||c0||^2
__device__ float g_smax[Bn];         // per-row max coarse score
__device__ float g_cand_val[(size_t)Bn * 48];
__device__ int   g_cand_idx[(size_t)Bn * 48];
__device__ float g_fourth[(size_t)Bn * 16];
__device__ int   g_idx[Bn];
__device__ float g_err[Bn];
__device__ float g_sum;

// ---------------- helpers ----------------
__device__ __forceinline__ uint32_t smem_u32(const void* p) {
    uint32_t a;
    asm("{ .reg .u64 t; cvta.to.shared.u64 t, %1; cvt.u32.u64 %0, t; }" : "=r"(a) : "l"(p));
    return a;
}
__device__ __forceinline__ void ldsm_x4(uint32_t r[4], uint32_t addr) {
    asm volatile("ldmatrix.sync.aligned.m8n8.x4.shared.b16 {%0,%1,%2,%3}, [%4];"
        : "=r"(r[0]), "=r"(r[1]), "=r"(r[2]), "=r"(r[3]) : "r"(addr));
}
__device__ __forceinline__ void mma_bf16(float d[4], const uint32_t a[4], const uint32_t b[2]) {
    asm volatile("mma.sync.aligned.m16n8k16.row.col.f32.bf16.bf16.f32 "
        "{%0,%1,%2,%3}, {%4,%5,%6,%7}, {%8,%9}, {%0,%1,%2,%3};"
        : "+f"(d[0]), "+f"(d[1]), "+f"(d[2]), "+f"(d[3])
        : "r"(a[0]), "r"(a[1]), "r"(a[2]), "r"(a[3]), "r"(b[0]), "r"(b[1]));
}
__device__ __forceinline__ uint32_t pack_bf16(float a, float b) {
    __nv_bfloat162 t = __floats2bfloat162_rn(a, b);
    return *(uint32_t*)&t;
}
__device__ __forceinline__ void cpasync16(uint32_t saddr, const void* g) {
    asm volatile("cp.async.cg.shared.global [%0], [%1], 16;" :: "r"(saddr), "l"(g));
}
#define CP_COMMIT() asm volatile("cp.async.commit_group;" ::: "memory")
#define CP_WAIT1()  asm volatile("cp.async.wait_group 1;" ::: "memory")
#define CP_WAIT0()  asm volatile("cp.async.wait_group 0;" ::: "memory")

// ---------------- encoder: X@W1+b1 -> LN -> GELU -> @W2+b2 (fp32 out) ----------------
__global__ void encoder_kernel(const float* __restrict__ X,
                               const float* __restrict__ W1, const float* __restrict__ b1,
                               const float* __restrict__ g1, const float* __restrict__ be1,
                               const float* __restrict__ W2, const float* __restrict__ b2)
{
    extern __shared__ float sm[];
    float* Xs = sm;
    float* Hs = sm + 32 * Dn;
    const int tid = threadIdx.x;
    const int row0 = blockIdx.x * 32;

    {
        const float4* Xg = (const float4*)(X + (size_t)row0 * Dn);
        float4* Xs4 = (float4*)Xs;
        for (int i = tid; i < 32 * Dn / 4; i += 256) Xs4[i] = Xg[i];
    }
    __syncthreads();

    const float4* Xs4 = (const float4*)Xs;
    float acc[32];
#pragma unroll
    for (int r = 0; r < 32; ++r) acc[r] = 0.f;
    const int col = tid;
    for (int d = 0; d < Dn; d += 4) {
        float w0 = W1[(d + 0) * Hn + col];
        float w1 = W1[(d + 1) * Hn + col];
        float w2 = W1[(d + 2) * Hn + col];
        float w3 = W1[(d + 3) * Hn + col];
#pragma unroll
        for (int r = 0; r < 32; ++r) {
            float4 x = Xs4[(r * Dn + d) >> 2];
            acc[r] = fmaf(x.x, w0, acc[r]);
            acc[r] = fmaf(x.y, w1, acc[r]);
            acc[r] = fmaf(x.z, w2, acc[r]);
            acc[r] = fmaf(x.w, w3, acc[r]);
        }
    }
    {
        float bb = b1[col];
#pragma unroll
        for (int r = 0; r < 32; ++r) Hs[r * Hn + col] = acc[r] + bb;
    }
    __syncthreads();

    {
        const int warp = tid >> 5, lane = tid & 31;
        for (int rr = 0; rr < 4; ++rr) {
            int r = warp + rr * 8;
            float s = 0.f, s2 = 0.f;
#pragma unroll
            for (int j = 0; j < 8; ++j) {
                float v = Hs[r * Hn + lane + j * 32];
                s += v; s2 += v * v;
            }
#pragma unroll
            for (int o = 16; o > 0; o >>= 1) {
                s  += __shfl_xor_sync(0xffffffff, s,  o);
                s2 += __shfl_xor_sync(0xffffffff, s2, o);
            }
            float mu  = s * (1.f / Hn);
            float var = s2 * (1.f / Hn) - mu * mu;
            float inv = rsqrtf(var + 1e-5f);
#pragma unroll
            for (int j = 0; j < 8; ++j) {
                int c = lane + j * 32;
                float v = (Hs[r * Hn + c] - mu) * inv * g1[c] + be1[c];
                Hs[r * Hn + c] = 0.5f * v * (1.f + erff(v * 0.70710678118654752f));
            }
        }
    }
    __syncthreads();

    {
        const float4* Hs4 = (const float4*)Hs;
        const int c2 = tid & 127;
        const int rbase = (tid >> 7) * 16;
        float a2[16];
#pragma unroll
        for (int r = 0; r < 16; ++r) a2[r] = 0.f;
        for (int d = 0; d < Hn; d += 4) {
            float w0 = W2[(d + 0) * Zn + c2];
            float w1 = W2[(d + 1) * Zn + c2];
            float w2 = W2[(d + 2) * Zn + c2];
            float w3 = W2[(d + 3) * Zn + c2];
#pragma unroll
            for (int r = 0; r < 16; ++r) {
                float4 h = Hs4[((rbase + r) * Hn + d) >> 2];
                a2[r] = fmaf(h.x, w0, a2[r]);
                a2[r] = fmaf(h.y, w1, a2[r]);
                a2[r] = fmaf(h.z, w2, a2[r]);
                a2[r] = fmaf(h.w, w3, a2[r]);
            }
        }
        float bb = b2[c2];
#pragma unroll
        for (int r = 0; r < 16; ++r)
            g_enc[(size_t)(row0 + rbase + r) * Zn + c2] = a2[r] + bb;
    }
}

// ---------------- per-row e0 + norms (warp per row) ----------------
__global__ void enorm_kernel()
{
    int gw = (blockIdx.x * 256 + threadIdx.x) >> 5;
    int lane = threadIdx.x & 31;
    const float4 e4 = ((const float4*)(g_enc + (size_t)gw * 128))[lane];
    float e0x = __bfloat162float(__float2bfloat16(e4.x));
    float e0y = __bfloat162float(__float2bfloat16(e4.y));
    float e0z = __bfloat162float(__float2bfloat16(e4.z));
    float e0w = __bfloat162float(__float2bfloat16(e4.w));
    ((uint2*)(g_e0 + (size_t)gw * 128))[lane] =
        make_uint2(pack_bf16(e4.x, e4.y), pack_bf16(e4.z, e4.w));
    float en2 = e4.x*e4.x + e4.y*e4.y + e4.z*e4.z + e4.w*e4.w;
    float dx = e4.x - e0x, dy = e4.y - e0y, dz = e4.z - e0z, dw = e4.w - e0w;
    float dn2 = dx*dx + dy*dy + dz*dz + dw*dw;
#pragma unroll
    for (int o = 16; o > 0; o >>= 1) {
        en2 += __shfl_xor_sync(0xffffffff, en2, o);
        dn2 += __shfl_xor_sync(0xffffffff, dn2, o);
    }
    if (lane == 0) { g_en2[gw] = en2; g_dn2[gw] = dn2; }
}

// ---------------- codebook: c0, -0.5||c||^2, max norms ----------------
__global__ void c0split_kernel(const float* __restrict__ C)
{
    int code = (blockIdx.x * 256 + threadIdx.x) >> 5;
    int lane = threadIdx.x & 31;
    const float4 c4 = ((const float4*)(C + (size_t)code * 128))[lane];
    float c0x = __bfloat162float(__float2bfloat16(c4.x));
    float c0y = __bfloat162float(__float2bfloat16(c4.y));
    float c0z = __bfloat162float(__float2bfloat16(c4.z));
    float c0w = __bfloat162float(__float2bfloat16(c4.w));
    ((uint2*)(g_c0 + (size_t)code * 128))[lane] =
        make_uint2(pack_bf16(c4.x, c4.y), pack_bf16(c4.z, c4.w));
    float c2 = c4.x*c4.x + c4.y*c4.y + c4.z*c4.z + c4.w*c4.w;
    float n2 = c0x*c0x + c0y*c0y + c0z*c0z + c0w*c0w;
    float dx = c4.x - c0x, dy = c4.y - c0y, dz = c4.z - c0z, dw = c4.w - c0w;
    float r2 = dx*dx + dy*dy + dz*dz + dw*dw;
#pragma unroll
    for (int o = 16; o > 0; o >>= 1) {
        c2 += __shfl_xor_sync(0xffffffff, c2, o);
        n2 += __shfl_xor_sync(0xffffffff, n2, o);
        r2 += __shfl_xor_sync(0xffffffff, r2, o);
    }
    if (lane == 0) {
        g_negc2[code] = -0.5f * c2;
        atomicMax((int*)&g_Rmax2, __float_as_int(r2));
        atomicMax((int*)&g_Nmax2, __float_as_int(n2));
    }
}

// ---------------- coarse distance: 64-row CTAs, 2 CTAs/SM, cp.async dbuf ----------------
#define LDK2 136
#define A_BYTES (64 * LDK2 * 2)         // 17408
#define TILE_BYTES (128 * LDK2 * 2)     // 34816
#define SB_A 0
#define SB_B0 A_BYTES
#define SB_RED (A_BYTES + 2 * TILE_BYTES)
#define DSM2_TOT (SB_RED + 64 * 16 * 4)

__global__ __launch_bounds__(256, 2) void dist_coarse_kernel()
{
    extern __shared__ char smem[];
    float* redsm = (float*)(smem + SB_RED);

    const int tid  = threadIdx.x;
    const int lane = tid & 31;
    const int wid  = tid >> 5;           // 0..7
    const int warp_m = wid >> 2;         // 0..1 (32-row bands)
    const int warp_n = wid & 3;          // 0..3 (32-code bands)
    const int row0 = blockIdx.x * 64;

    const uint32_t sbA  = smem_u32(smem) + SB_A;
    const uint32_t sbB0 = smem_u32(smem) + SB_B0;

    // prologue: async load resident A (group), then B tile 0 (group)
    for (int i = tid; i < 1024; i += 256) {
        int r = i >> 4, u = i & 15;
        cpasync16(sbA + r * (LDK2 * 2) + u * 16,
                  g_e0 + (size_t)(row0 + r) * 128 + u * 8);
    }
    CP_COMMIT();
    for (int i = tid; i < 2048; i += 256) {
        int r = i >> 4, u = i & 15;
        cpasync16(sbB0 + r * (LDK2 * 2) + u * 16,
                  g_c0 + (size_t)r * 128 + u * 8);
    }
    CP_COMMIT();

    uint32_t a_addr[2];
#pragma unroll
    for (int mi = 0; mi < 2; ++mi)
        a_addr[mi] = sbA + ((warp_m * 32 + mi * 16 + (lane & 15)) * LDK2 + (lane >> 4) * 8) * 2;
    uint32_t b_addr[2];
#pragma unroll
    for (int njp = 0; njp < 2; ++njp)
        b_addr[njp] = sbB0 + ((warp_n * 32 + njp * 16 + (lane & 7) + ((lane >> 4) << 3)) * LDK2
                              + ((lane >> 3) & 1) * 8) * 2;

    // top-4 values, top-3 idx, per row (4 rows per thread)
    float v1[4], v2[4], v3[4], v4[4];
    int   i1[4], i2[4], i3[4];
#pragma unroll
    for (int r = 0; r < 4; ++r) {
        v1[r] = v2[r] = v3[r] = v4[r] = -INFINITY;
        i1[r] = i2[r] = i3[r] = 0;
    }

    const int cq = (lane & 3) * 2;

    for (int t = 0, kt = 0; t < 128; ++t, kt += 128) {
        const uint32_t bufo = (uint32_t)(t & 1) * TILE_BYTES;
        if (t < 127) {
            uint32_t sb = sbB0 + ((t + 1) & 1) * TILE_BYTES;
            const __nv_bfloat16* src = g_c0 + (size_t)(kt + 128) * 128;
            for (int i = tid; i < 2048; i += 256) {
                int r = i >> 4, u = i & 15;
                cpasync16(sb + r * (LDK2 * 2) + u * 16, src + (size_t)r * 128 + u * 8);
            }
            CP_COMMIT();
            CP_WAIT1();
        } else {
            CP_WAIT0();
        }
        __syncthreads();

        float nc[8];
#pragma unroll
        for (int nj = 0; nj < 4; ++nj) {
            nc[nj * 2]     = g_negc2[kt + warp_n * 32 + nj * 8 + cq];
            nc[nj * 2 + 1] = g_negc2[kt + warp_n * 32 + nj * 8 + cq + 1];
        }

        float acc[2][4][4];
#pragma unroll
        for (int mi = 0; mi < 2; ++mi)
#pragma unroll
            for (int nj = 0; nj < 4; ++nj)
#pragma unroll
                for (int k = 0; k < 4; ++k) acc[mi][nj][k] = 0.f;

#pragma unroll
        for (int s = 0; s < 8; ++s) {
            uint32_t af[2][4], bf[2][4];
#pragma unroll
            for (int mi = 0; mi < 2; ++mi) ldsm_x4(af[mi], a_addr[mi] + s * 32);
#pragma unroll
            for (int njp = 0; njp < 2; ++njp) ldsm_x4(bf[njp], b_addr[njp] + bufo + s * 32);
#pragma unroll
            for (int mi = 0; mi < 2; ++mi)
#pragma unroll
                for (int nj = 0; nj < 4; ++nj)
                    mma_bf16(acc[mi][nj], af[mi], bf[nj >> 1] + (nj & 1) * 2);
        }

        // epilogue: max-of-8 quick reject, then rare insert
#pragma unroll
        for (int mi = 0; mi < 2; ++mi) {
#pragma unroll
            for (int h = 0; h < 2; ++h) {
                const int ri = mi * 2 + h;
                float s0 = acc[mi][0][h * 2]     + nc[0];
                float s1 = acc[mi][0][h * 2 + 1] + nc[1];
                float s2 = acc[mi][1][h * 2]     + nc[2];
                float s3 = acc[mi][1][h * 2 + 1] + nc[3];
                float s4 = acc[mi][2][h * 2]     + nc[4];
                float s5 = acc[mi][2][h * 2 + 1] + nc[5];
                float s6 = acc[mi][3][h * 2]     + nc[6];
                float s7 = acc[mi][3][h * 2 + 1] + nc[7];
                float m8 = fmaxf(fmaxf(fmaxf(s0, s1), fmaxf(s2, s3)),
                                 fmaxf(fmaxf(s4, s5), fmaxf(s6, s7)));
                if (m8 > v4[ri]) {
                    float sv[8] = {s0, s1, s2, s3, s4, s5, s6, s7};
#pragma unroll
                    for (int j = 0; j < 8; ++j) {
                        float v = sv[j];
                        if (v > v4[ri]) {
                            int idx = kt + warp_n * 32 + (j >> 1) * 8 + cq + (j & 1);
                            if (v > v1[ri]) {
                                v4[ri] = v3[ri]; v3[ri] = v2[ri]; i3[ri] = i2[ri];
                                v2[ri] = v1[ri]; i2[ri] = i1[ri];
                                v1[ri] = v; i1[ri] = idx;
                            } else if (v > v2[ri]) {
                                v4[ri] = v3[ri]; v3[ri] = v2[ri]; i3[ri] = i2[ri];
                                v2[ri] = v; i2[ri] = idx;
                            } else if (v > v3[ri]) {
                                v4[ri] = v3[ri]; v3[ri] = v; i3[ri] = idx;
                            } else {
                                v4[ri] = v;
                            }
                        }
                    }
                }
            }
        }
        __syncthreads();
    }

    // write candidates + v4; reduce smax
    const int slot = warp_n * 4 + (lane & 3);
#pragma unroll
    for (int ri = 0; ri < 4; ++ri) {
        int mi = ri >> 1, h = ri & 1;
        int lrow = warp_m * 32 + mi * 16 + (lane >> 2) + h * 8;
        size_t row = (size_t)(row0 + lrow);
        g_cand_val[row * 48 + slot * 3]     = v1[ri];
        g_cand_idx[row * 48 + slot * 3]     = i1[ri];
        g_cand_val[row * 48 + slot * 3 + 1] = v2[ri];
        g_cand_idx[row * 48 + slot * 3 + 1] = i2[ri];
        g_cand_val[row * 48 + slot * 3 + 2] = v3[ri];
        g_cand_idx[row * 48 + slot * 3 + 2] = i3[ri];
        g_fourth[row * 16 + slot] = v4[ri];
        redsm[lrow * 16 + slot] = v1[ri];
    }
    __syncthreads();
    if (tid < 64) {
        float m = redsm[tid * 16];
#pragma unroll
        for (int w = 1; w < 16; ++w) m = fmaxf(m, redsm[tid * 16 + w]);
        g_smax[row0 + tid] = m;
    }
}

// ---------------- exact rescore of candidates (warp per row) ----------------
__global__ void rescore_kernel(const float* __restrict__ CB)
{
    const int r = blockIdx.x * 4 + (threadIdx.x >> 5);
    const int lane = threadIdx.x & 31;

    float delta = sqrtf(g_en2[r]) * sqrtf(g_Rmax2) + sqrtf(g_dn2[r]) * sqrtf(g_Nmax2);
    float thresh = g_smax[r] - 1.05f * delta - 1e-4f;

    float th = (lane < 16) ? g_fourth[(size_t)r * 16 + lane] : -INFINITY;
    bool flag = __ballot_sync(0xffffffff, th >= thresh) != 0;

    const float4 e4 = ((const float4*)(g_enc + (size_t)r * 128))[lane];

    float bs = -INFINITY;
    int bi = 0x7fffffff;

    if (!flag) {
        for (int s = 0; s < 48; ++s) {
            float v = g_cand_val[(size_t)r * 48 + s];
            if (v >= thresh) {
                int idx = g_cand_idx[(size_t)r * 48 + s];
                float4 c4 = ((const float4*)(CB + (size_t)idx * 128))[lane];
                float d = e4.x*c4.x + e4.y*c4.y + e4.z*c4.z + e4.w*c4.w;
#pragma unroll
                for (int o = 16; o > 0; o >>= 1) d += __shfl_xor_sync(0xffffffff, d, o);
                float sx = d + g_negc2[idx];
                if (sx > bs || (sx == bs && idx < bi)) { bs = sx; bi = idx; }
            }
        }
    } else {
        for (int k = 0; k < Kn; ++k) {
            float4 c4 = ((const float4*)(CB + (size_t)k * 128))[lane];
            float d = e4.x*c4.x + e4.y*c4.y + e4.z*c4.z + e4.w*c4.w;
#pragma unroll
            for (int o = 16; o > 0; o >>= 1) d += __shfl_xor_sync(0xffffffff, d, o);
            float sx = d + g_negc2[k];
            if (sx > bs) { bs = sx; bi = k; }
        }
    }
    if (lane == 0) g_idx[r] = bi;
}

// ---------------- decoder ----------------
__global__ void decoder_kernel(const float* __restrict__ C,
                               const float* __restrict__ W3, const float* __restrict__ b3,
                               const float* __restrict__ g2, const float* __restrict__ be2,
                               const float* __restrict__ W4, const float* __restrict__ b4,
                               const float* __restrict__ X)
{
    extern __shared__ float sm[];
    float* Qs = sm;
    float* Hs = sm + 32 * Zn;
    float* ep = Hs + 32 * Hn;
    const int tid = threadIdx.x;
    const int row0 = blockIdx.x * 32;

    for (int i = tid; i < 32 * 32; i += 256) {
        int r = i >> 5, d4 = i & 31;
        int code = g_idx[row0 + r];
        ((float4*)Qs)[r * 32 + d4] = ((const float4*)C)[(size_t)code * 32 + d4];
    }
    __syncthreads();

    {
        const float4* Qs4 = (const float4*)Qs;
        float acc[32];
#pragma unroll
        for (int r = 0; r < 32; ++r) acc[r] = 0.f;
        const int col = tid;
        for (int d = 0; d < Zn; d += 4) {
            float w0 = W3[(d + 0) * Hn + col];
            float w1 = W3[(d + 1) * Hn + col];
            float w2 = W3[(d + 2) * Hn + col];
            float w3 = W3[(d + 3) * Hn + col];
#pragma unroll
            for (int r = 0; r < 32; ++r) {
                float4 q = Qs4[(r * Zn + d) >> 2];
                acc[r] = fmaf(q.x, w0, acc[r]);
                acc[r] = fmaf(q.y, w1, acc[r]);
                acc[r] = fmaf(q.z, w2, acc[r]);
                acc[r] = fmaf(q.w, w3, acc[r]);
            }
        }
        float bb = b3[col];
#pragma unroll
        for (int r = 0; r < 32; ++r) Hs[r * Hn + col] = acc[r] + bb;
    }
    __syncthreads();

    {
        const int warp = tid >> 5, lane = tid & 31;
        for (int rr = 0; rr < 4; ++rr) {
            int r = warp + rr * 8;
            float s = 0.f, s2 = 0.f;
#pragma unroll
            for (int j = 0; j < 8; ++j) {
                float v = Hs[r * Hn + lane + j * 32];
                s += v; s2 += v * v;
            }
#pragma unroll
            for (int o = 16; o > 0; o >>= 1) {
                s  += __shfl_xor_sync(0xffffffff, s,  o);
                s2 += __shfl_xor_sync(0xffffffff, s2, o);
            }
            float mu  = s * (1.f / Hn);
            float var = s2 * (1.f / Hn) - mu * mu;
            float inv = rsqrtf(var + 1e-5f);
#pragma unroll
            for (int j = 0; j < 8; ++j) {
                int c = lane + j * 32;
                float v = (Hs[r * Hn + c] - mu) * inv * g2[c] + be2[c];
                Hs[r * Hn + c] = 0.5f * v * (1.f + erff(v * 0.70710678118654752f));
            }
        }
    }
    __syncthreads();

    float aA[32], aB[32];
#pragma unroll
    for (int r = 0; r < 32; ++r) { aA[r] = 0.f; aB[r] = 0.f; }
    {
        const float4* Hs4 = (const float4*)Hs;
        for (int d = 0; d < Hn; d += 4) {
            float wa0 = W4[(d + 0) * Dn + tid];
            float wa1 = W4[(d + 1) * Dn + tid];
            float wa2 = W4[(d + 2) * Dn + tid];
            float wa3 = W4[(d + 3) * Dn + tid];
            float wb0 = W4[(d + 0) * Dn + tid + 256];
            float wb1 = W4[(d + 1) * Dn + tid + 256];
            float wb2 = W4[(d + 2) * Dn + tid + 256];
            float wb3 = W4[(d + 3) * Dn + tid + 256];
#pragma unroll
            for (int r = 0; r < 32; ++r) {
                float4 h = Hs4[(r * Hn + d) >> 2];
                aA[r] = fmaf(h.x, wa0, aA[r]);
                aA[r] = fmaf(h.y, wa1, aA[r]);
                aA[r] = fmaf(h.z, wa2, aA[r]);
                aA[r] = fmaf(h.w, wa3, aA[r]);
                aB[r] = fmaf(h.x, wb0, aB[r]);
                aB[r] = fmaf(h.y, wb1, aB[r]);
                aB[r] = fmaf(h.z, wb2, aB[r]);
                aB[r] = fmaf(h.w, wb3, aB[r]);
            }
        }
    }

    {
        const int warp = tid >> 5, lane = tid & 31;
        float b4a = b4[tid], b4b = b4[tid + 256];
        for (int r = 0; r < 32; ++r) {
            float f1 = X[(size_t)(row0 + r) * Dn + tid];
            float f2 = X[(size_t)(row0 + r) * Dn + tid + 256];
            float d1 = aA[r] + b4a - f1;
            float d2 = aB[r] + b4b - f2;
            float e = d1 * d1 + d2 * d2;
#pragma unroll
            for (int o = 16; o > 0; o >>= 1) e += __shfl_xor_sync(0xffffffff, e, o);
            if (lane == 0) ep[r * 8 + warp] = e;
        }
        __syncthreads();
        if (tid < 32) {
            float s = 0.f;
#pragma unroll
            for (int w = 0; w < 8; ++w) s += ep[tid * 8 + w];
            g_err[row0 + tid] = s * (1.f / Dn);
        }
    }
}

// ---------------- global mean ----------------
__global__ void reduce_kernel()
{
    __shared__ float s[256];
    int tid = threadIdx.x;
    float a = 0.f;
    for (int i = tid; i < Bn; i += 256) a += g_err[i];
    s[tid] = a;
    __syncthreads();
    for (int o = 128; o > 0; o >>= 1) {
        if (tid < o) s[tid] += s[tid + o];
        __syncthreads();
    }
    if (tid == 0) g_sum = s[0];
}

// ---------------- MDL + output ----------------
__global__ void final_kernel(float* __restrict__ out)
{
    int i = blockIdx.x * 256 + threadIdx.x;
    float scale = g_sum * (1.f / Bn) + 1e-8f;
    float err = g_err[i];
    float eb = (fabsf(err) / scale + logf(2.f * scale)) * 1.4426950408889634f;
    float tb = 14.f + eb;
    out[i]          = err;
    out[Bn + i]     = (Dn * 32.f) / tb;
    out[2 * Bn + i] = tb;
    out[3 * Bn + i] = (float)g_idx[i];
}

// ---------------- launch ----------------
extern "C" void kernel_launch(void* const* d_in, const int* in_sizes, int n_in,
                              void* d_out, int out_size)
{
    const float* X   = (const float*)d_in[0];
    const float* W1  = (const float*)d_in[1];
    const float* b1  = (const float*)d_in[2];
    const float* g1  = (const float*)d_in[3];
    const float* be1 = (const float*)d_in[4];
    const float* W2  = (const float*)d_in[5];
    const float* b2  = (const float*)d_in[6];
    const float* CB  = (const float*)d_in[7];
    const float* W3  = (const float*)d_in[8];
    const float* b3  = (const float*)d_in[9];
    const float* g2  = (const float*)d_in[10];
    const float* be2 = (const float*)d_in[11];
    const float* W4  = (const float*)d_in[12];
    const float* b4  = (const float*)d_in[13];
    float* out = (float*)d_out;

    cudaFuncSetAttribute(encoder_kernel,     cudaFuncAttributeMaxDynamicSharedMemorySize, 98304);
    cudaFuncSetAttribute(dist_coarse_kernel, cudaFuncAttributeMaxDynamicSharedMemorySize, DSM2_TOT);
    cudaFuncSetAttribute(decoder_kernel,     cudaFuncAttributeMaxDynamicSharedMemorySize, 50176);

    c0split_kernel<<<Kn / 8, 256>>>(CB);
    encoder_kernel<<<Bn / 32, 256, 98304>>>(X, W1, b1, g1, be1, W2, b2);
    enorm_kernel<<<Bn / 8, 256>>>();
    dist_coarse_kernel<<<Bn / 64, 256, DSM2_TOT>>>();
    rescore_kernel<<<Bn / 4, 128>>>(CB);
    decoder_kernel<<<Bn / 32, 256, 50176>>>(CB, W3, b3, g2, be2, W4, b4, X);
    reduce_kernel<<<1, 256>>>();
    final_kernel<<<Bn / 256, 256>>>(out);
}